// round 9
// baseline (speedup 1.0000x reference)
#include <cuda_runtime.h>
#include <math.h>
#include <stdint.h>

// ---------------- problem constants ----------------
#define NNODES   100000
#define NEDGES   600000
#define NEDGES2  1500000
#define HID      128
#define HF4      32
#define NB       64
#define WT_LAYER 8192
#define SCAN_BS  1024

// ---------------- scratch (ping-pong feature buffers) ----------------------
__device__ float g_hA[(size_t)NNODES * HID];
__device__ float g_hB[(size_t)NNODES * HID];
__device__ float g_eA[(size_t)NEDGES * HID];
__device__ float g_eB[(size_t)NEDGES * HID];

struct ZB {
    int degN[2 * NNODES];         // [out | in]
    int degE[2 * NEDGES];
    int cnt [2 * NB];
    float pool[NB * 256];
};
__device__ ZB  g_zb;
__device__ int g_offN[NNODES];
__device__ int g_curN[NNODES];
__device__ int g_offE[NEDGES];
__device__ int g_curE[NEDGES];
__device__ int g_csrN[NEDGES];
__device__ int g_csrE[NEDGES2];
__device__ int g_bsum[SCAN_BS];
__device__ float g_Wt[6 * WT_LAYER * 2];

// ---------------- helpers ----------------
__device__ __forceinline__ void red_add_v2(float* addr, float x, float y) {
    asm volatile("red.global.add.v2.f32 [%0], {%1,%2};"
                 :: "l"(addr), "f"(x), "f"(y) : "memory");
}
__device__ __forceinline__ uint32_t f2tf32(float f) {
    uint32_t r;
    asm("cvt.rna.tf32.f32 %0, %1;" : "=r"(r) : "f"(f));
    return r;
}
__device__ __forceinline__ void mma_tf32(float& c0, float& c1, float& c2, float& c3,
                                         uint32_t a0, uint32_t a1, uint32_t a2, uint32_t a3,
                                         uint32_t b0, uint32_t b1) {
    asm volatile("mma.sync.aligned.m16n8k8.row.col.f32.tf32.tf32.f32 "
                 "{%0,%1,%2,%3}, {%4,%5,%6,%7}, {%8,%9}, {%0,%1,%2,%3};"
                 : "+f"(c0), "+f"(c1), "+f"(c2), "+f"(c3)
                 : "r"(a0), "r"(a1), "r"(a2), "r"(a3), "r"(b0), "r"(b1));
}
__device__ __forceinline__ float rsdeg_i(int d) {
    return rsqrtf(fmaxf((float)d, 1.f));
}

// ---------------- small kernels ----------------
__global__ void k_zero_all() {
    long n4 = sizeof(ZB) / 16;
    float4* p = (float4*)&g_zb;
    long i = (long)blockIdx.x * blockDim.x + threadIdx.x;
    if (i < n4) p[i] = make_float4(0.f, 0.f, 0.f, 0.f);
}

__global__ void k_wt(const float* __restrict__ gW, const float* __restrict__ lgW,
                     float* __restrict__ Wt) {
    int idx = blockIdx.x * blockDim.x + threadIdx.x;
    if (idx >= 6 * WT_LAYER) return;
    int layer = idx >> 13;
    int rem = idx & 8191;
    int ks = rem >> 9;
    int rem2 = rem & 511;
    int nf = rem2 >> 5, lane = rem2 & 31;
    int g = lane >> 2, tig = lane & 3;
    int n = nf * 8 + g, k = ks * 8 + tig;
    const float* W = (layer < 3) ? (gW + (long)layer * 16384)
                                 : (lgW + (long)(layer - 3) * 16384);
    Wt[(long)idx * 2 + 0] = __uint_as_float(f2tf32(__ldg(W + k * HID + n)));
    Wt[(long)idx * 2 + 1] = __uint_as_float(f2tf32(__ldg(W + (k + 4) * HID + n)));
}

__global__ void k_deg(const int* __restrict__ s, const int* __restrict__ t,
                      int* deg, int noff, int n) {
    int i = blockIdx.x * blockDim.x + threadIdx.x;
    if (i < n) {
        atomicAdd(deg + s[i], 1);
        atomicAdd(deg + noff + t[i], 1);
    }
}

__global__ void k_cnt(const int* __restrict__ seg, int* __restrict__ cnt,
                      int cntoff, int n) {
    __shared__ int h[NB];
    int t = threadIdx.x;
    if (t < NB) h[t] = 0;
    __syncthreads();
    int i = blockIdx.x * blockDim.x + t;
    if (i < n) atomicAdd(h + seg[i], 1);
    __syncthreads();
    if (t < NB && h[t]) atomicAdd(cnt + cntoff + t, h[t]);
}

__global__ void k_scan1(const int* __restrict__ deg, int* __restrict__ off,
                        int* __restrict__ bsum, int n) {
    __shared__ int sh[SCAN_BS];
    int t = threadIdx.x;
    int i = blockIdx.x * SCAN_BS + t;
    int v = (i < n) ? deg[i] : 0;
    sh[t] = v;
    __syncthreads();
    for (int s = 1; s < SCAN_BS; s <<= 1) {
        int add = (t >= s) ? sh[t - s] : 0;
        __syncthreads();
        sh[t] += add;
        __syncthreads();
    }
    if (i < n) off[i] = sh[t] - v;
    if (t == SCAN_BS - 1) bsum[blockIdx.x] = sh[t];
}
__global__ void k_scan2(int* bsum, int nb) {
    __shared__ int sh[SCAN_BS];
    int t = threadIdx.x;
    int v = (t < nb) ? bsum[t] : 0;
    sh[t] = v;
    __syncthreads();
    for (int s = 1; s < SCAN_BS; s <<= 1) {
        int add = (t >= s) ? sh[t - s] : 0;
        __syncthreads();
        sh[t] += add;
        __syncthreads();
    }
    if (t < nb) bsum[t] = sh[t] - v;
}
__global__ void k_scan3(int* __restrict__ off, const int* __restrict__ bsum,
                        int* __restrict__ cur, int n) {
    int i = blockIdx.x * blockDim.x + threadIdx.x;
    if (i < n) {
        int o = off[i] + bsum[i >> 10];
        off[i] = o;
        cur[i] = o;
    }
}
__global__ void k_fill(const int* __restrict__ s, const int* __restrict__ t,
                       int* __restrict__ cur, int* __restrict__ csr, int n) {
    int i = blockIdx.x * blockDim.x + threadIdx.x;
    if (i < n) {
        int p = atomicAdd(cur + t[i], 1);
        csr[p] = s[i];
    }
}

// ---------------- fused CSR-gather + tensor-core GEMM ----------------------
// 256 threads / 8 warps per 64-row tile.
// Phase 1: 8 rows gathered per warp.  Phase 2: warp = 16 rows x 64 cols.
// MODE 0: f = feat[s];  MODE 1: f = d[s]*ep_w + ep_b;  MODE 2: f = emb[z[s]]
// EPI  0: store rows;   EPI  1: red.add into pool[seg[row]*256 + coloff + n]
// 'feat' and 'out' must be distinct buffers (ping-pong).
#define XS_STRIDE 132
template<int MODE, int EPI>
__global__ void __launch_bounds__(256)
k_conv(const float* __restrict__ feat, const int* __restrict__ z,
       const float* __restrict__ emb, const float* __restrict__ epw,
       const float* __restrict__ epb,
       const int* __restrict__ dego, const int* __restrict__ degi,
       const int* __restrict__ off, const int* __restrict__ csr,
       const float2* __restrict__ Wt, const float* __restrict__ bias,
       float* __restrict__ out, const int* __restrict__ seg,
       float* __restrict__ pool, int coloff, int rows) {
    __shared__ __align__(16) uint32_t Xs[64 * XS_STRIDE];
    int tid = threadIdx.x;
    int warp = tid >> 5, lane = tid & 31;
    int g = lane >> 2, tig = lane & 3;
    long r0 = (long)blockIdx.x * 64;

    // ---- phase 1: gather A-tile (8 rows per warp) ----
    float4 wv, bv;
    if (MODE == 1) { wv = ((const float4*)epw)[lane]; bv = ((const float4*)epb)[lane]; }
    for (int rl = warp; rl < 64; rl += 8) {
        long r = r0 + rl;
        float4 acc = make_float4(0.f, 0.f, 0.f, 0.f);
        float si = 0.f;
        if (r < rows) {
            int beg = __ldg(off + r), dg = __ldg(degi + r);
            for (int j = beg; j < beg + dg; j++) {
                int s = __ldg(csr + j);
                float sc = rsdeg_i(__ldg(dego + s));
                if (MODE == 0) {
                    float4 v = __ldg((const float4*)feat + (long)s * HF4 + lane);
                    acc.x += v.x * sc; acc.y += v.y * sc;
                    acc.z += v.z * sc; acc.w += v.w * sc;
                } else if (MODE == 1) {
                    float dv = __ldg(feat + s) * sc;   // feat == d
                    acc.x += dv * wv.x + bv.x * sc;
                    acc.y += dv * wv.y + bv.y * sc;
                    acc.z += dv * wv.z + bv.z * sc;
                    acc.w += dv * wv.w + bv.w * sc;
                } else {
                    int zi = __ldg(z + s);
                    float4 v = __ldg((const float4*)emb + (long)zi * HF4 + lane);
                    acc.x += v.x * sc; acc.y += v.y * sc;
                    acc.z += v.z * sc; acc.w += v.w * sc;
                }
            }
            si = rsdeg_i(dg);
        }
        uint32_t* p = Xs + rl * XS_STRIDE + lane * 4;
        p[0] = f2tf32(acc.x * si); p[1] = f2tf32(acc.y * si);
        p[2] = f2tf32(acc.z * si); p[3] = f2tf32(acc.w * si);
    }
    __syncthreads();

    // ---- phase 2: warp = 16 rows x 64 cols ----
    int rg = warp & 3;     // row group (16 rows)
    int ch = warp >> 2;    // column half (64 cols)
    float acc[8][4];
#pragma unroll
    for (int nf = 0; nf < 8; nf++)
#pragma unroll
        for (int j = 0; j < 4; j++) acc[nf][j] = 0.f;

    const uint32_t* xa = Xs + (rg * 16 + g) * XS_STRIDE + tig;
    const uint2* wt = ((const uint2*)Wt) + lane;
#pragma unroll 4
    for (int ks = 0; ks < 16; ks++) {
        int k0 = ks * 8;
        uint32_t a0 = xa[k0];
        uint32_t a1 = xa[8 * XS_STRIDE + k0];
        uint32_t a2 = xa[k0 + 4];
        uint32_t a3 = xa[8 * XS_STRIDE + k0 + 4];
#pragma unroll
        for (int nf = 0; nf < 8; nf++) {
            uint2 b = __ldg(wt + (ks * 16 + ch * 8 + nf) * 32);
            mma_tf32(acc[nf][0], acc[nf][1], acc[nf][2], acc[nf][3],
                     a0, a1, a2, a3, b.x, b.y);
        }
    }

    long row0 = r0 + rg * 16 + g;
    long row1 = row0 + 8;
    int seg0 = 0, seg1 = 0;
    if (EPI == 1) {
        if (row0 < rows) seg0 = __ldg(seg + row0);
        if (row1 < rows) seg1 = __ldg(seg + row1);
    }
#pragma unroll
    for (int nf = 0; nf < 8; nf++) {
        int n0 = (ch * 8 + nf) * 8 + 2 * tig;
        float b0 = __ldg(bias + n0), b1 = __ldg(bias + n0 + 1);
        if (row0 < rows) {
            float ox = fmaxf(acc[nf][0] + b0, 0.f);
            float oy = fmaxf(acc[nf][1] + b1, 0.f);
            if (EPI == 0) *(float2*)(out + row0 * HID + n0) = make_float2(ox, oy);
            else red_add_v2(pool + (long)seg0 * 256 + coloff + n0, ox, oy);
        }
        if (row1 < rows) {
            float ox = fmaxf(acc[nf][2] + b0, 0.f);
            float oy = fmaxf(acc[nf][3] + b1, 0.f);
            if (EPI == 0) *(float2*)(out + row1 * HID + n0) = make_float2(ox, oy);
            else red_add_v2(pool + (long)seg1 * 256 + coloff + n0, ox, oy);
        }
    }
}

// final MLP
__global__ void k_readout(const float* __restrict__ pool, const int* __restrict__ cnt,
                          const float* __restrict__ r1w, const float* __restrict__ r1b,
                          const float* __restrict__ r2w, const float* __restrict__ r2b,
                          float* __restrict__ out) {
    __shared__ float x[256];
    __shared__ float redbuf[128];
    int g = blockIdx.x, tid = threadIdx.x;
    float cn = fmaxf((float)cnt[g], 1.f);
    float ce = fmaxf((float)cnt[NB + g], 1.f);
    x[tid]       = pool[g * 256 + tid] / cn;
    x[128 + tid] = pool[g * 256 + 128 + tid] / ce;
    __syncthreads();
    float a = r1b[tid];
#pragma unroll 8
    for (int k = 0; k < 256; k++) a += x[k] * r1w[k * 128 + tid];
    float sig = 1.f / (1.f + expf(-a));
    float p = a * sig * r2w[tid];
    redbuf[tid] = p;
    __syncthreads();
    for (int s = 64; s > 0; s >>= 1) {
        if (tid < s) redbuf[tid] += redbuf[tid + s];
        __syncthreads();
    }
    if (tid == 0) out[g] = redbuf[0] + r2b[0];
}

// ---------------- launch ----------------
static inline int cdiv(long a, long b) { return (int)((a + b - 1) / b); }

extern "C" void kernel_launch(void* const* d_in, const int* in_sizes, int n_in,
                              void* d_out, int out_size) {
    const int*   z    = (const int*)  d_in[0];
    const float* d    = (const float*)d_in[1];
    const int*   src  = (const int*)  d_in[2];
    const int*   dst  = (const int*)  d_in[3];
    const int*   lsrc = (const int*)  d_in[4];
    const int*   ldst = (const int*)  d_in[5];
    const int*   ng   = (const int*)  d_in[6];
    const int*   eg   = (const int*)  d_in[7];
    const float* emb  = (const float*)d_in[8];
    const float* epw  = (const float*)d_in[9];
    const float* epb  = (const float*)d_in[10];
    const float* gW   = (const float*)d_in[11];
    const float* gb   = (const float*)d_in[12];
    const float* lgW  = (const float*)d_in[13];
    const float* lgb  = (const float*)d_in[14];
    const float* r1w  = (const float*)d_in[15];
    const float* r1b  = (const float*)d_in[16];
    const float* r2w  = (const float*)d_in[17];
    const float* r2b  = (const float*)d_in[18];
    float* out = (float*)d_out;

    float *p_hA, *p_hB, *p_eA, *p_eB, *p_Wt;
    int *p_offN, *p_curN, *p_offE, *p_curE, *p_csrN, *p_csrE, *p_bsum;
    ZB* p_zb;
    cudaGetSymbolAddress((void**)&p_hA,   g_hA);
    cudaGetSymbolAddress((void**)&p_hB,   g_hB);
    cudaGetSymbolAddress((void**)&p_eA,   g_eA);
    cudaGetSymbolAddress((void**)&p_eB,   g_eB);
    cudaGetSymbolAddress((void**)&p_zb,   g_zb);
    cudaGetSymbolAddress((void**)&p_offN, g_offN);
    cudaGetSymbolAddress((void**)&p_curN, g_curN);
    cudaGetSymbolAddress((void**)&p_offE, g_offE);
    cudaGetSymbolAddress((void**)&p_curE, g_curE);
    cudaGetSymbolAddress((void**)&p_csrN, g_csrN);
    cudaGetSymbolAddress((void**)&p_csrE, g_csrE);
    cudaGetSymbolAddress((void**)&p_bsum, g_bsum);
    cudaGetSymbolAddress((void**)&p_Wt,   g_Wt);

    int* p_degNo = p_zb->degN;
    int* p_degNi = p_zb->degN + NNODES;
    int* p_degEo = p_zb->degE;
    int* p_degEi = p_zb->degE + NEDGES;
    int* p_cnt   = p_zb->cnt;
    float* p_pool = p_zb->pool;

    const float2* wtL[6];
    for (int l = 0; l < 6; l++) wtL[l] = (const float2*)p_Wt + (long)l * WT_LAYER;

    const int T = 256;

    k_zero_all<<<cdiv(sizeof(ZB) / 16, T), T>>>();
    k_wt<<<cdiv(6 * WT_LAYER, T), T>>>(gW, lgW, p_Wt);
    k_cnt<<<cdiv(NNODES, T), T>>>(ng, p_cnt, 0, NNODES);
    k_cnt<<<cdiv(NEDGES, T), T>>>(eg, p_cnt, NB, NEDGES);

    // ---- CSR build: line graph ----
    k_deg<<<cdiv(NEDGES2, T), T>>>(lsrc, ldst, p_degEo, NEDGES, NEDGES2);
    k_scan1<<<cdiv(NEDGES, SCAN_BS), SCAN_BS>>>(p_degEi, p_offE, p_bsum, NEDGES);
    k_scan2<<<1, SCAN_BS>>>(p_bsum, cdiv(NEDGES, SCAN_BS));
    k_scan3<<<cdiv(NEDGES, T), T>>>(p_offE, p_bsum, p_curE, NEDGES);
    k_fill<<<cdiv(NEDGES2, T), T>>>(lsrc, ldst, p_curE, p_csrE, NEDGES2);
    // ---- CSR build: node graph ----
    k_deg<<<cdiv(NEDGES, T), T>>>(src, dst, p_degNo, NNODES, NEDGES);
    k_scan1<<<cdiv(NNODES, SCAN_BS), SCAN_BS>>>(p_degNi, p_offN, p_bsum, NNODES);
    k_scan2<<<1, SCAN_BS>>>(p_bsum, cdiv(NNODES, SCAN_BS));
    k_scan3<<<cdiv(NNODES, T), T>>>(p_offN, p_bsum, p_curN, NNODES);
    k_fill<<<cdiv(NEDGES, T), T>>>(src, dst, p_curN, p_csrN, NEDGES);

    const int gE = cdiv(NEDGES, 64), gN = cdiv(NNODES, 64);

    // ---- line graph layers (fused gather+gemm, ping-pong e buffers) ----
    k_conv<1, 0><<<gE, 256>>>(d, nullptr, nullptr, epw, epb,
                              p_degEo, p_degEi, p_offE, p_csrE,
                              wtL[3], lgb, p_eA, nullptr, nullptr, 0, NEDGES);
    k_conv<0, 0><<<gE, 256>>>(p_eA, nullptr, nullptr, nullptr, nullptr,
                              p_degEo, p_degEi, p_offE, p_csrE,
                              wtL[4], lgb + HID, p_eB, nullptr, nullptr, 0, NEDGES);
    k_conv<0, 1><<<gE, 256>>>(p_eB, nullptr, nullptr, nullptr, nullptr,
                              p_degEo, p_degEi, p_offE, p_csrE,
                              wtL[5], lgb + 2 * HID, nullptr, eg, p_pool, 128, NEDGES);
    // ---- node graph layers (ping-pong h buffers) ----
    k_conv<2, 0><<<gN, 256>>>(nullptr, z, emb, nullptr, nullptr,
                              p_degNo, p_degNi, p_offN, p_csrN,
                              wtL[0], gb, p_hA, nullptr, nullptr, 0, NNODES);
    k_conv<0, 0><<<gN, 256>>>(p_hA, nullptr, nullptr, nullptr, nullptr,
                              p_degNo, p_degNi, p_offN, p_csrN,
                              wtL[1], gb + HID, p_hB, nullptr, nullptr, 0, NNODES);
    k_conv<0, 1><<<gN, 256>>>(p_hB, nullptr, nullptr, nullptr, nullptr,
                              p_degNo, p_degNi, p_offN, p_csrN,
                              wtL[2], gb + 2 * HID, nullptr, ng, p_pool, 0, NNODES);

    // ---- readout ----
    k_readout<<<NB, 128>>>(p_pool, p_cnt, r1w, r1b, r2w, r2b, out);
}

// round 10
// speedup vs baseline: 1.6022x; 1.6022x over previous
#include <cuda_runtime.h>
#include <math.h>
#include <stdint.h>

// ---------------- problem constants ----------------
#define NNODES   100000
#define NEDGES   600000
#define NEDGES2  1500000
#define HID      128
#define HF4      32
#define NB       64
#define WT_LAYER 8192
#define SCAN_BS  1024

// ---------------- scratch (ping-pong feature buffers) ----------------------
__device__ float g_hA[(size_t)NNODES * HID];
__device__ float g_hB[(size_t)NNODES * HID];
__device__ float g_eA[(size_t)NEDGES * HID];
__device__ float g_eB[(size_t)NEDGES * HID];

struct ZB {
    int degN[2 * NNODES];         // [out | in]
    int degE[2 * NEDGES];
    int cnt [2 * NB];
    float pool[NB * 256];
};
__device__ ZB  g_zb;
__device__ int g_offN[NNODES];
__device__ int g_curN[NNODES];
__device__ int g_offE[NEDGES];
__device__ int g_curE[NEDGES];
__device__ int g_csrN[NEDGES];
__device__ int g_csrE[NEDGES2];
__device__ int g_bsumE[SCAN_BS];
__device__ int g_bsumN[SCAN_BS];
__device__ float g_Wt[6 * WT_LAYER * 2];

// ---------------- helpers ----------------
__device__ __forceinline__ void red_add_v2(float* addr, float x, float y) {
    asm volatile("red.global.add.v2.f32 [%0], {%1,%2};"
                 :: "l"(addr), "f"(x), "f"(y) : "memory");
}
__device__ __forceinline__ uint32_t f2tf32(float f) {
    uint32_t r;
    asm("cvt.rna.tf32.f32 %0, %1;" : "=r"(r) : "f"(f));
    return r;
}
__device__ __forceinline__ void mma_tf32(float& c0, float& c1, float& c2, float& c3,
                                         uint32_t a0, uint32_t a1, uint32_t a2, uint32_t a3,
                                         uint32_t b0, uint32_t b1) {
    asm volatile("mma.sync.aligned.m16n8k8.row.col.f32.tf32.tf32.f32 "
                 "{%0,%1,%2,%3}, {%4,%5,%6,%7}, {%8,%9}, {%0,%1,%2,%3};"
                 : "+f"(c0), "+f"(c1), "+f"(c2), "+f"(c3)
                 : "r"(a0), "r"(a1), "r"(a2), "r"(a3), "r"(b0), "r"(b1));
}
__device__ __forceinline__ float rsdeg_i(int d) {
    return rsqrtf(fmaxf((float)d, 1.f));
}

// ---------------- small kernels ----------------
__global__ void k_zero_all() {
    long n4 = sizeof(ZB) / 16;
    float4* p = (float4*)&g_zb;
    long i = (long)blockIdx.x * blockDim.x + threadIdx.x;
    if (i < n4) p[i] = make_float4(0.f, 0.f, 0.f, 0.f);
}

__global__ void k_wt(const float* __restrict__ gW, const float* __restrict__ lgW,
                     float* __restrict__ Wt) {
    int idx = blockIdx.x * blockDim.x + threadIdx.x;
    if (idx >= 6 * WT_LAYER) return;
    int layer = idx >> 13;
    int rem = idx & 8191;
    int ks = rem >> 9;
    int rem2 = rem & 511;
    int nf = rem2 >> 5, lane = rem2 & 31;
    int g = lane >> 2, tig = lane & 3;
    int n = nf * 8 + g, k = ks * 8 + tig;
    const float* W = (layer < 3) ? (gW + (long)layer * 16384)
                                 : (lgW + (long)(layer - 3) * 16384);
    Wt[(long)idx * 2 + 0] = __uint_as_float(f2tf32(__ldg(W + k * HID + n)));
    Wt[(long)idx * 2 + 1] = __uint_as_float(f2tf32(__ldg(W + (k + 4) * HID + n)));
}

__global__ void k_deg(const int* __restrict__ s, const int* __restrict__ t,
                      int* deg, int noff, int n) {
    int i = blockIdx.x * blockDim.x + threadIdx.x;
    if (i < n) {
        atomicAdd(deg + s[i], 1);
        atomicAdd(deg + noff + t[i], 1);
    }
}

__global__ void k_cnt(const int* __restrict__ seg, int* __restrict__ cnt,
                      int cntoff, int n) {
    __shared__ int h[NB];
    int t = threadIdx.x;
    if (t < NB) h[t] = 0;
    __syncthreads();
    int i = blockIdx.x * blockDim.x + t;
    if (i < n) atomicAdd(h + seg[i], 1);
    __syncthreads();
    if (t < NB && h[t]) atomicAdd(cnt + cntoff + t, h[t]);
}

__global__ void k_scan1(const int* __restrict__ deg, int* __restrict__ off,
                        int* __restrict__ bsum, int n) {
    __shared__ int sh[SCAN_BS];
    int t = threadIdx.x;
    int i = blockIdx.x * SCAN_BS + t;
    int v = (i < n) ? deg[i] : 0;
    sh[t] = v;
    __syncthreads();
    for (int s = 1; s < SCAN_BS; s <<= 1) {
        int add = (t >= s) ? sh[t - s] : 0;
        __syncthreads();
        sh[t] += add;
        __syncthreads();
    }
    if (i < n) off[i] = sh[t] - v;
    if (t == SCAN_BS - 1) bsum[blockIdx.x] = sh[t];
}
__global__ void k_scan2(int* bsum, int nb) {
    __shared__ int sh[SCAN_BS];
    int t = threadIdx.x;
    int v = (t < nb) ? bsum[t] : 0;
    sh[t] = v;
    __syncthreads();
    for (int s = 1; s < SCAN_BS; s <<= 1) {
        int add = (t >= s) ? sh[t - s] : 0;
        __syncthreads();
        sh[t] += add;
        __syncthreads();
    }
    if (t < nb) bsum[t] = sh[t] - v;
}
__global__ void k_scan3(int* __restrict__ off, const int* __restrict__ bsum,
                        int* __restrict__ cur, int n) {
    int i = blockIdx.x * blockDim.x + threadIdx.x;
    if (i < n) {
        int o = off[i] + bsum[i >> 10];
        off[i] = o;
        cur[i] = o;
    }
}
__global__ void k_fill(const int* __restrict__ s, const int* __restrict__ t,
                       int* __restrict__ cur, int* __restrict__ csr, int n) {
    int i = blockIdx.x * blockDim.x + threadIdx.x;
    if (i < n) {
        int p = atomicAdd(cur + t[i], 1);
        csr[p] = s[i];
    }
}

// ---------------- fused CSR-gather + tensor-core GEMM (round-7 body) -------
// MODE 0: f = feat[s];  MODE 1: f = d[s]*ep_w + ep_b;  MODE 2: f = emb[z[s]]
// EPI  0: store rows;   EPI  1: red.add into pool[seg[row]*256 + coloff + n]
// 'feat' and 'out' must be distinct buffers (ping-pong).
#define XS_STRIDE 132
template<int MODE, int EPI>
__global__ void __launch_bounds__(128)
k_conv(const float* __restrict__ feat, const int* __restrict__ z,
       const float* __restrict__ emb, const float* __restrict__ epw,
       const float* __restrict__ epb,
       const int* __restrict__ dego, const int* __restrict__ degi,
       const int* __restrict__ off, const int* __restrict__ csr,
       const float2* __restrict__ Wt, const float* __restrict__ bias,
       float* __restrict__ out, const int* __restrict__ seg,
       float* __restrict__ pool, int coloff, int rows) {
    __shared__ __align__(16) uint32_t Xs[64 * XS_STRIDE];
    int tid = threadIdx.x;
    int warp = tid >> 5, lane = tid & 31;
    int g = lane >> 2, tig = lane & 3;
    long r0 = (long)blockIdx.x * 64;

    // ---- phase 1: gather A-tile (warp per row, 16 rows per warp) ----
    float4 wv, bv;
    if (MODE == 1) { wv = ((const float4*)epw)[lane]; bv = ((const float4*)epb)[lane]; }
    for (int rl = warp; rl < 64; rl += 4) {
        long r = r0 + rl;
        float4 acc = make_float4(0.f, 0.f, 0.f, 0.f);
        float si = 0.f;
        if (r < rows) {
            int beg = __ldg(off + r), dg = __ldg(degi + r);
            for (int j = beg; j < beg + dg; j++) {
                int s = __ldg(csr + j);
                float sc = rsdeg_i(__ldg(dego + s));
                if (MODE == 0) {
                    float4 v = __ldg((const float4*)feat + (long)s * HF4 + lane);
                    acc.x += v.x * sc; acc.y += v.y * sc;
                    acc.z += v.z * sc; acc.w += v.w * sc;
                } else if (MODE == 1) {
                    float dv = __ldg(feat + s) * sc;   // feat == d
                    acc.x += dv * wv.x + bv.x * sc;
                    acc.y += dv * wv.y + bv.y * sc;
                    acc.z += dv * wv.z + bv.z * sc;
                    acc.w += dv * wv.w + bv.w * sc;
                } else {
                    int zi = __ldg(z + s);
                    float4 v = __ldg((const float4*)emb + (long)zi * HF4 + lane);
                    acc.x += v.x * sc; acc.y += v.y * sc;
                    acc.z += v.z * sc; acc.w += v.w * sc;
                }
            }
            si = rsdeg_i(dg);
        }
        uint32_t* p = Xs + rl * XS_STRIDE + lane * 4;
        p[0] = f2tf32(acc.x * si); p[1] = f2tf32(acc.y * si);
        p[2] = f2tf32(acc.z * si); p[3] = f2tf32(acc.w * si);
    }
    __syncthreads();

    // ---- phase 2: 64x128 @ 128x128 tf32 MMA ----
    float acc[16][4];
#pragma unroll
    for (int nf = 0; nf < 16; nf++)
#pragma unroll
        for (int j = 0; j < 4; j++) acc[nf][j] = 0.f;

    const uint32_t* xa = Xs + (warp * 16 + g) * XS_STRIDE + tig;
    const uint2* wt = ((const uint2*)Wt) + lane;
#pragma unroll 4
    for (int ks = 0; ks < 16; ks++) {
        int k0 = ks * 8;
        uint32_t a0 = xa[k0];
        uint32_t a1 = xa[8 * XS_STRIDE + k0];
        uint32_t a2 = xa[k0 + 4];
        uint32_t a3 = xa[8 * XS_STRIDE + k0 + 4];
#pragma unroll
        for (int nf = 0; nf < 16; nf++) {
            uint2 b = __ldg(wt + (ks * 16 + nf) * 32);
            mma_tf32(acc[nf][0], acc[nf][1], acc[nf][2], acc[nf][3],
                     a0, a1, a2, a3, b.x, b.y);
        }
    }

    long row0 = r0 + warp * 16 + g;
    long row1 = row0 + 8;
    int seg0 = 0, seg1 = 0;
    if (EPI == 1) {
        if (row0 < rows) seg0 = __ldg(seg + row0);
        if (row1 < rows) seg1 = __ldg(seg + row1);
    }
#pragma unroll
    for (int nf = 0; nf < 16; nf++) {
        int n0 = nf * 8 + 2 * tig;
        float b0 = __ldg(bias + n0), b1 = __ldg(bias + n0 + 1);
        if (row0 < rows) {
            float ox = fmaxf(acc[nf][0] + b0, 0.f);
            float oy = fmaxf(acc[nf][1] + b1, 0.f);
            if (EPI == 0) *(float2*)(out + row0 * HID + n0) = make_float2(ox, oy);
            else red_add_v2(pool + (long)seg0 * 256 + coloff + n0, ox, oy);
        }
        if (row1 < rows) {
            float ox = fmaxf(acc[nf][2] + b0, 0.f);
            float oy = fmaxf(acc[nf][3] + b1, 0.f);
            if (EPI == 0) *(float2*)(out + row1 * HID + n0) = make_float2(ox, oy);
            else red_add_v2(pool + (long)seg1 * 256 + coloff + n0, ox, oy);
        }
    }
}

// final MLP
__global__ void k_readout(const float* __restrict__ pool, const int* __restrict__ cnt,
                          const float* __restrict__ r1w, const float* __restrict__ r1b,
                          const float* __restrict__ r2w, const float* __restrict__ r2b,
                          float* __restrict__ out) {
    __shared__ float x[256];
    __shared__ float redbuf[128];
    int g = blockIdx.x, tid = threadIdx.x;
    float cn = fmaxf((float)cnt[g], 1.f);
    float ce = fmaxf((float)cnt[NB + g], 1.f);
    x[tid]       = pool[g * 256 + tid] / cn;
    x[128 + tid] = pool[g * 256 + 128 + tid] / ce;
    __syncthreads();
    float a = r1b[tid];
#pragma unroll 8
    for (int k = 0; k < 256; k++) a += x[k] * r1w[k * 128 + tid];
    float sig = 1.f / (1.f + expf(-a));
    float p = a * sig * r2w[tid];
    redbuf[tid] = p;
    __syncthreads();
    for (int s = 64; s > 0; s >>= 1) {
        if (tid < s) redbuf[tid] += redbuf[tid + s];
        __syncthreads();
    }
    if (tid == 0) out[g] = redbuf[0] + r2b[0];
}

// ---------------- launch ----------------
static inline int cdiv(long a, long b) { return (int)((a + b - 1) / b); }

extern "C" void kernel_launch(void* const* d_in, const int* in_sizes, int n_in,
                              void* d_out, int out_size) {
    const int*   z    = (const int*)  d_in[0];
    const float* d    = (const float*)d_in[1];
    const int*   src  = (const int*)  d_in[2];
    const int*   dst  = (const int*)  d_in[3];
    const int*   lsrc = (const int*)  d_in[4];
    const int*   ldst = (const int*)  d_in[5];
    const int*   ng   = (const int*)  d_in[6];
    const int*   eg   = (const int*)  d_in[7];
    const float* emb  = (const float*)d_in[8];
    const float* epw  = (const float*)d_in[9];
    const float* epb  = (const float*)d_in[10];
    const float* gW   = (const float*)d_in[11];
    const float* gb   = (const float*)d_in[12];
    const float* lgW  = (const float*)d_in[13];
    const float* lgb  = (const float*)d_in[14];
    const float* r1w  = (const float*)d_in[15];
    const float* r1b  = (const float*)d_in[16];
    const float* r2w  = (const float*)d_in[17];
    const float* r2b  = (const float*)d_in[18];
    float* out = (float*)d_out;

    float *p_hA, *p_hB, *p_eA, *p_eB, *p_Wt;
    int *p_offN, *p_curN, *p_offE, *p_curE, *p_csrN, *p_csrE, *p_bsumE, *p_bsumN;
    ZB* p_zb;
    cudaGetSymbolAddress((void**)&p_hA,    g_hA);
    cudaGetSymbolAddress((void**)&p_hB,    g_hB);
    cudaGetSymbolAddress((void**)&p_eA,    g_eA);
    cudaGetSymbolAddress((void**)&p_eB,    g_eB);
    cudaGetSymbolAddress((void**)&p_zb,    g_zb);
    cudaGetSymbolAddress((void**)&p_offN,  g_offN);
    cudaGetSymbolAddress((void**)&p_curN,  g_curN);
    cudaGetSymbolAddress((void**)&p_offE,  g_offE);
    cudaGetSymbolAddress((void**)&p_curE,  g_curE);
    cudaGetSymbolAddress((void**)&p_csrN,  g_csrN);
    cudaGetSymbolAddress((void**)&p_csrE,  g_csrE);
    cudaGetSymbolAddress((void**)&p_bsumE, g_bsumE);
    cudaGetSymbolAddress((void**)&p_bsumN, g_bsumN);
    cudaGetSymbolAddress((void**)&p_Wt,    g_Wt);

    int* p_degNo = p_zb->degN;
    int* p_degNi = p_zb->degN + NNODES;
    int* p_degEo = p_zb->degE;
    int* p_degEi = p_zb->degE + NEDGES;
    int* p_cnt   = p_zb->cnt;
    float* p_pool = p_zb->pool;

    const float2* wtL[6];
    for (int l = 0; l < 6; l++) wtL[l] = (const float2*)p_Wt + (long)l * WT_LAYER;

    const int T = 256;
    const int gE = cdiv(NEDGES, 64), gN = cdiv(NNODES, 64);

    // fork resources (created per call, never destroyed — host-side only,
    // kernel_launch is invoked only a handful of times before graph replay)
    cudaStream_t s2;
    cudaStreamCreateWithFlags(&s2, cudaStreamNonBlocking);
    cudaEvent_t evRoot, evNode;
    cudaEventCreateWithFlags(&evRoot, cudaEventDisableTiming);
    cudaEventCreateWithFlags(&evNode, cudaEventDisableTiming);

    // ---- common prologue (main stream) ----
    k_zero_all<<<cdiv(sizeof(ZB) / 16, T), T>>>();
    k_wt<<<cdiv(6 * WT_LAYER, T), T>>>(gW, lgW, p_Wt);
    cudaEventRecord(evRoot, 0);

    // ---- node chain on s2 (independent of line chain until readout) ----
    cudaStreamWaitEvent(s2, evRoot, 0);
    k_deg<<<cdiv(NEDGES, T), T, 0, s2>>>(src, dst, p_degNo, NNODES, NEDGES);
    k_scan1<<<cdiv(NNODES, SCAN_BS), SCAN_BS, 0, s2>>>(p_degNi, p_offN, p_bsumN, NNODES);
    k_scan2<<<1, SCAN_BS, 0, s2>>>(p_bsumN, cdiv(NNODES, SCAN_BS));
    k_scan3<<<cdiv(NNODES, T), T, 0, s2>>>(p_offN, p_bsumN, p_curN, NNODES);
    k_fill<<<cdiv(NEDGES, T), T, 0, s2>>>(src, dst, p_curN, p_csrN, NEDGES);
    k_conv<2, 0><<<gN, 128, 0, s2>>>(nullptr, z, emb, nullptr, nullptr,
                                     p_degNo, p_degNi, p_offN, p_csrN,
                                     wtL[0], gb, p_hA, nullptr, nullptr, 0, NNODES);
    k_conv<0, 0><<<gN, 128, 0, s2>>>(p_hA, nullptr, nullptr, nullptr, nullptr,
                                     p_degNo, p_degNi, p_offN, p_csrN,
                                     wtL[1], gb + HID, p_hB, nullptr, nullptr, 0, NNODES);
    k_conv<0, 1><<<gN, 128, 0, s2>>>(p_hB, nullptr, nullptr, nullptr, nullptr,
                                     p_degNo, p_degNi, p_offN, p_csrN,
                                     wtL[2], gb + 2 * HID, nullptr, ng, p_pool, 0, NNODES);
    k_cnt<<<cdiv(NNODES, T), T, 0, s2>>>(ng, p_cnt, 0, NNODES);
    k_cnt<<<cdiv(NEDGES, T), T, 0, s2>>>(eg, p_cnt, NB, NEDGES);
    cudaEventRecord(evNode, s2);

    // ---- line chain on main stream ----
    k_deg<<<cdiv(NEDGES2, T), T>>>(lsrc, ldst, p_degEo, NEDGES, NEDGES2);
    k_scan1<<<cdiv(NEDGES, SCAN_BS), SCAN_BS>>>(p_degEi, p_offE, p_bsumE, NEDGES);
    k_scan2<<<1, SCAN_BS>>>(p_bsumE, cdiv(NEDGES, SCAN_BS));
    k_scan3<<<cdiv(NEDGES, T), T>>>(p_offE, p_bsumE, p_curE, NEDGES);
    k_fill<<<cdiv(NEDGES2, T), T>>>(lsrc, ldst, p_curE, p_csrE, NEDGES2);
    k_conv<1, 0><<<gE, 128>>>(d, nullptr, nullptr, epw, epb,
                              p_degEo, p_degEi, p_offE, p_csrE,
                              wtL[3], lgb, p_eA, nullptr, nullptr, 0, NEDGES);
    k_conv<0, 0><<<gE, 128>>>(p_eA, nullptr, nullptr, nullptr, nullptr,
                              p_degEo, p_degEi, p_offE, p_csrE,
                              wtL[4], lgb + HID, p_eB, nullptr, nullptr, 0, NEDGES);
    k_conv<0, 1><<<gE, 128>>>(p_eB, nullptr, nullptr, nullptr, nullptr,
                              p_degEo, p_degEi, p_offE, p_csrE,
                              wtL[5], lgb + 2 * HID, nullptr, eg, p_pool, 128, NEDGES);

    // ---- join + readout ----
    cudaStreamWaitEvent(0, evNode, 0);
    k_readout<<<NB, 128>>>(p_pool, p_cnt, r1w, r1b, r2w, r2b, out);
}

// round 11
// speedup vs baseline: 1.7829x; 1.1128x over previous
#include <cuda_runtime.h>
#include <cuda_fp16.h>
#include <math.h>
#include <stdint.h>

// ---------------- problem constants ----------------
#define NNODES   100000
#define NEDGES   600000
#define NEDGES2  1500000
#define HID      128
#define HF4      32
#define NB       64
#define WT_LAYER 8192
#define SCAN_BS  1024

// ---------------- scratch ----------------
// intermediate features in fp16 (line-graph buffer now fits L2)
__device__ __half g_hA[(size_t)NNODES * HID];
__device__ __half g_hB[(size_t)NNODES * HID];
__device__ __half g_eA[(size_t)NEDGES * HID];
__device__ __half g_eB[(size_t)NEDGES * HID];

struct ZB {
    int degN[2 * NNODES];         // [out | in]
    int degE[2 * NEDGES];
    int cnt [2 * NB];
    float pool[NB * 256];
};
__device__ ZB  g_zb;
__device__ int g_offN[NNODES];
__device__ int g_curN[NNODES];
__device__ int g_offE[NEDGES];
__device__ int g_curE[NEDGES];
__device__ int2 g_csrN[NEDGES];    // (src, rsdeg_out(src) as float bits)
__device__ int2 g_csrE[NEDGES2];
__device__ int g_bsumE[SCAN_BS];
__device__ int g_bsumN[SCAN_BS];
__device__ float g_Wt[6 * WT_LAYER * 2];

// ---------------- helpers ----------------
__device__ __forceinline__ void red_add_v2(float* addr, float x, float y) {
    asm volatile("red.global.add.v2.f32 [%0], {%1,%2};"
                 :: "l"(addr), "f"(x), "f"(y) : "memory");
}
__device__ __forceinline__ uint32_t f2tf32(float f) {
    uint32_t r;
    asm("cvt.rna.tf32.f32 %0, %1;" : "=r"(r) : "f"(f));
    return r;
}
__device__ __forceinline__ void mma_tf32(float& c0, float& c1, float& c2, float& c3,
                                         uint32_t a0, uint32_t a1, uint32_t a2, uint32_t a3,
                                         uint32_t b0, uint32_t b1) {
    asm volatile("mma.sync.aligned.m16n8k8.row.col.f32.tf32.tf32.f32 "
                 "{%0,%1,%2,%3}, {%4,%5,%6,%7}, {%8,%9}, {%0,%1,%2,%3};"
                 : "+f"(c0), "+f"(c1), "+f"(c2), "+f"(c3)
                 : "r"(a0), "r"(a1), "r"(a2), "r"(a3), "r"(b0), "r"(b1));
}
__device__ __forceinline__ float rsdeg_i(int d) {
    return rsqrtf(fmaxf((float)d, 1.f));
}

// ---------------- small kernels ----------------
__global__ void k_zero_all() {
    long n4 = sizeof(ZB) / 16;
    float4* p = (float4*)&g_zb;
    long i = (long)blockIdx.x * blockDim.x + threadIdx.x;
    if (i < n4) p[i] = make_float4(0.f, 0.f, 0.f, 0.f);
}

__global__ void k_wt(const float* __restrict__ gW, const float* __restrict__ lgW,
                     float* __restrict__ Wt) {
    int idx = blockIdx.x * blockDim.x + threadIdx.x;
    if (idx >= 6 * WT_LAYER) return;
    int layer = idx >> 13;
    int rem = idx & 8191;
    int ks = rem >> 9;
    int rem2 = rem & 511;
    int nf = rem2 >> 5, lane = rem2 & 31;
    int g = lane >> 2, tig = lane & 3;
    int n = nf * 8 + g, k = ks * 8 + tig;
    const float* W = (layer < 3) ? (gW + (long)layer * 16384)
                                 : (lgW + (long)(layer - 3) * 16384);
    Wt[(long)idx * 2 + 0] = __uint_as_float(f2tf32(__ldg(W + k * HID + n)));
    Wt[(long)idx * 2 + 1] = __uint_as_float(f2tf32(__ldg(W + (k + 4) * HID + n)));
}

__global__ void k_deg(const int* __restrict__ s, const int* __restrict__ t,
                      int* deg, int noff, int n) {
    int i = blockIdx.x * blockDim.x + threadIdx.x;
    if (i < n) {
        atomicAdd(deg + s[i], 1);
        atomicAdd(deg + noff + t[i], 1);
    }
}

__global__ void k_cnt(const int* __restrict__ seg, int* __restrict__ cnt,
                      int cntoff, int n) {
    __shared__ int h[NB];
    int t = threadIdx.x;
    if (t < NB) h[t] = 0;
    __syncthreads();
    int i = blockIdx.x * blockDim.x + t;
    if (i < n) atomicAdd(h + seg[i], 1);
    __syncthreads();
    if (t < NB && h[t]) atomicAdd(cnt + cntoff + t, h[t]);
}

__global__ void k_scan1(const int* __restrict__ deg, int* __restrict__ off,
                        int* __restrict__ bsum, int n) {
    __shared__ int sh[SCAN_BS];
    int t = threadIdx.x;
    int i = blockIdx.x * SCAN_BS + t;
    int v = (i < n) ? deg[i] : 0;
    sh[t] = v;
    __syncthreads();
    for (int s = 1; s < SCAN_BS; s <<= 1) {
        int add = (t >= s) ? sh[t - s] : 0;
        __syncthreads();
        sh[t] += add;
        __syncthreads();
    }
    if (i < n) off[i] = sh[t] - v;
    if (t == SCAN_BS - 1) bsum[blockIdx.x] = sh[t];
}
__global__ void k_scan2(int* bsum, int nb) {
    __shared__ int sh[SCAN_BS];
    int t = threadIdx.x;
    int v = (t < nb) ? bsum[t] : 0;
    sh[t] = v;
    __syncthreads();
    for (int s = 1; s < SCAN_BS; s <<= 1) {
        int add = (t >= s) ? sh[t - s] : 0;
        __syncthreads();
        sh[t] += add;
        __syncthreads();
    }
    if (t < nb) bsum[t] = sh[t] - v;
}
__global__ void k_scan3(int* __restrict__ off, const int* __restrict__ bsum,
                        int* __restrict__ cur, int n) {
    int i = blockIdx.x * blockDim.x + threadIdx.x;
    if (i < n) {
        int o = off[i] + bsum[i >> 10];
        off[i] = o;
        cur[i] = o;
    }
}
// fill CSR with (src, rsdeg_out(src)) pairs — removes a dependent load
// from every edge of every conv layer.
__global__ void k_fill(const int* __restrict__ s, const int* __restrict__ t,
                       const int* __restrict__ dego,
                       int* __restrict__ cur, int2* __restrict__ csr, int n) {
    int i = blockIdx.x * blockDim.x + threadIdx.x;
    if (i < n) {
        int si = s[i];
        float sc = rsdeg_i(__ldg(dego + si));
        int p = atomicAdd(cur + t[i], 1);
        csr[p] = make_int2(si, __float_as_int(sc));
    }
}

// ---------------- fused CSR-gather + tensor-core GEMM ----------------------
// MODE 0: f = feat16[s] (fp16);  MODE 1: f = d[s]*ep_w + ep_b;  MODE 2: f = emb[z[s]]
// EPI  0: store rows as fp16;    EPI  1: red.add into pool (fp32)
// gather source and 'out16' must be distinct buffers (ping-pong).
#define XS_STRIDE 132
template<int MODE, int EPI>
__global__ void __launch_bounds__(128)
k_conv(const __half* __restrict__ feat16, const float* __restrict__ dvec,
       const int* __restrict__ z, const float* __restrict__ emb,
       const float* __restrict__ epw, const float* __restrict__ epb,
       const int* __restrict__ degi,
       const int* __restrict__ off, const int2* __restrict__ csr,
       const float2* __restrict__ Wt, const float* __restrict__ bias,
       __half* __restrict__ out16, const int* __restrict__ seg,
       float* __restrict__ pool, int coloff, int rows) {
    __shared__ __align__(16) uint32_t Xs[64 * XS_STRIDE];
    int tid = threadIdx.x;
    int warp = tid >> 5, lane = tid & 31;
    int g = lane >> 2, tig = lane & 3;
    long r0 = (long)blockIdx.x * 64;

    // ---- phase 1: gather A-tile (warp per row, 16 rows per warp) ----
    float4 wv, bv;
    if (MODE == 1) { wv = ((const float4*)epw)[lane]; bv = ((const float4*)epb)[lane]; }
    for (int rl = warp; rl < 64; rl += 4) {
        long r = r0 + rl;
        float4 acc = make_float4(0.f, 0.f, 0.f, 0.f);
        float si = 0.f;
        if (r < rows) {
            int beg = __ldg(off + r), dg = __ldg(degi + r);
            for (int j = beg; j < beg + dg; j++) {
                int2 en = __ldg(csr + j);
                int s = en.x;
                float sc = __int_as_float(en.y);
                if (MODE == 0) {
                    uint2 raw = __ldg((const uint2*)feat16 + (long)s * 32 + lane);
                    float2 f0 = __half22float2(*(__half2*)&raw.x);
                    float2 f1 = __half22float2(*(__half2*)&raw.y);
                    acc.x += f0.x * sc; acc.y += f0.y * sc;
                    acc.z += f1.x * sc; acc.w += f1.y * sc;
                } else if (MODE == 1) {
                    float dv = __ldg(dvec + s) * sc;
                    acc.x += dv * wv.x + bv.x * sc;
                    acc.y += dv * wv.y + bv.y * sc;
                    acc.z += dv * wv.z + bv.z * sc;
                    acc.w += dv * wv.w + bv.w * sc;
                } else {
                    int zi = __ldg(z + s);
                    float4 v = __ldg((const float4*)emb + (long)zi * HF4 + lane);
                    acc.x += v.x * sc; acc.y += v.y * sc;
                    acc.z += v.z * sc; acc.w += v.w * sc;
                }
            }
            si = rsdeg_i(dg);
        }
        uint32_t* p = Xs + rl * XS_STRIDE + lane * 4;
        p[0] = f2tf32(acc.x * si); p[1] = f2tf32(acc.y * si);
        p[2] = f2tf32(acc.z * si); p[3] = f2tf32(acc.w * si);
    }
    __syncthreads();

    // ---- phase 2: 64x128 @ 128x128 tf32 MMA ----
    float acc[16][4];
#pragma unroll
    for (int nf = 0; nf < 16; nf++)
#pragma unroll
        for (int j = 0; j < 4; j++) acc[nf][j] = 0.f;

    const uint32_t* xa = Xs + (warp * 16 + g) * XS_STRIDE + tig;
    const uint2* wt = ((const uint2*)Wt) + lane;
#pragma unroll 4
    for (int ks = 0; ks < 16; ks++) {
        int k0 = ks * 8;
        uint32_t a0 = xa[k0];
        uint32_t a1 = xa[8 * XS_STRIDE + k0];
        uint32_t a2 = xa[k0 + 4];
        uint32_t a3 = xa[8 * XS_STRIDE + k0 + 4];
#pragma unroll
        for (int nf = 0; nf < 16; nf++) {
            uint2 b = __ldg(wt + (ks * 16 + nf) * 32);
            mma_tf32(acc[nf][0], acc[nf][1], acc[nf][2], acc[nf][3],
                     a0, a1, a2, a3, b.x, b.y);
        }
    }

    long row0 = r0 + warp * 16 + g;
    long row1 = row0 + 8;
    int seg0 = 0, seg1 = 0;
    if (EPI == 1) {
        if (row0 < rows) seg0 = __ldg(seg + row0);
        if (row1 < rows) seg1 = __ldg(seg + row1);
    }
#pragma unroll
    for (int nf = 0; nf < 16; nf++) {
        int n0 = nf * 8 + 2 * tig;
        float b0 = __ldg(bias + n0), b1 = __ldg(bias + n0 + 1);
        if (row0 < rows) {
            float ox = fmaxf(acc[nf][0] + b0, 0.f);
            float oy = fmaxf(acc[nf][1] + b1, 0.f);
            if (EPI == 0) *(__half2*)(out16 + row0 * HID + n0) = __floats2half2_rn(ox, oy);
            else red_add_v2(pool + (long)seg0 * 256 + coloff + n0, ox, oy);
        }
        if (row1 < rows) {
            float ox = fmaxf(acc[nf][2] + b0, 0.f);
            float oy = fmaxf(acc[nf][3] + b1, 0.f);
            if (EPI == 0) *(__half2*)(out16 + row1 * HID + n0) = __floats2half2_rn(ox, oy);
            else red_add_v2(pool + (long)seg1 * 256 + coloff + n0, ox, oy);
        }
    }
}

// final MLP
__global__ void k_readout(const float* __restrict__ pool, const int* __restrict__ cnt,
                          const float* __restrict__ r1w, const float* __restrict__ r1b,
                          const float* __restrict__ r2w, const float* __restrict__ r2b,
                          float* __restrict__ out) {
    __shared__ float x[256];
    __shared__ float redbuf[128];
    int g = blockIdx.x, tid = threadIdx.x;
    float cn = fmaxf((float)cnt[g], 1.f);
    float ce = fmaxf((float)cnt[NB + g], 1.f);
    x[tid]       = pool[g * 256 + tid] / cn;
    x[128 + tid] = pool[g * 256 + 128 + tid] / ce;
    __syncthreads();
    float a = r1b[tid];
#pragma unroll 8
    for (int k = 0; k < 256; k++) a += x[k] * r1w[k * 128 + tid];
    float sig = 1.f / (1.f + expf(-a));
    float p = a * sig * r2w[tid];
    redbuf[tid] = p;
    __syncthreads();
    for (int s = 64; s > 0; s >>= 1) {
        if (tid < s) redbuf[tid] += redbuf[tid + s];
        __syncthreads();
    }
    if (tid == 0) out[g] = redbuf[0] + r2b[0];
}

// ---------------- launch ----------------
static inline int cdiv(long a, long b) { return (int)((a + b - 1) / b); }

extern "C" void kernel_launch(void* const* d_in, const int* in_sizes, int n_in,
                              void* d_out, int out_size) {
    const int*   z    = (const int*)  d_in[0];
    const float* d    = (const float*)d_in[1];
    const int*   src  = (const int*)  d_in[2];
    const int*   dst  = (const int*)  d_in[3];
    const int*   lsrc = (const int*)  d_in[4];
    const int*   ldst = (const int*)  d_in[5];
    const int*   ng   = (const int*)  d_in[6];
    const int*   eg   = (const int*)  d_in[7];
    const float* emb  = (const float*)d_in[8];
    const float* epw  = (const float*)d_in[9];
    const float* epb  = (const float*)d_in[10];
    const float* gW   = (const float*)d_in[11];
    const float* gb   = (const float*)d_in[12];
    const float* lgW  = (const float*)d_in[13];
    const float* lgb  = (const float*)d_in[14];
    const float* r1w  = (const float*)d_in[15];
    const float* r1b  = (const float*)d_in[16];
    const float* r2w  = (const float*)d_in[17];
    const float* r2b  = (const float*)d_in[18];
    float* out = (float*)d_out;

    __half *p_hA, *p_hB, *p_eA, *p_eB;
    float *p_Wt;
    int *p_offN, *p_curN, *p_offE, *p_curE, *p_bsumE, *p_bsumN;
    int2 *p_csrN, *p_csrE;
    ZB* p_zb;
    cudaGetSymbolAddress((void**)&p_hA,    g_hA);
    cudaGetSymbolAddress((void**)&p_hB,    g_hB);
    cudaGetSymbolAddress((void**)&p_eA,    g_eA);
    cudaGetSymbolAddress((void**)&p_eB,    g_eB);
    cudaGetSymbolAddress((void**)&p_zb,    g_zb);
    cudaGetSymbolAddress((void**)&p_offN,  g_offN);
    cudaGetSymbolAddress((void**)&p_curN,  g_curN);
    cudaGetSymbolAddress((void**)&p_offE,  g_offE);
    cudaGetSymbolAddress((void**)&p_curE,  g_curE);
    cudaGetSymbolAddress((void**)&p_csrN,  g_csrN);
    cudaGetSymbolAddress((void**)&p_csrE,  g_csrE);
    cudaGetSymbolAddress((void**)&p_bsumE, g_bsumE);
    cudaGetSymbolAddress((void**)&p_bsumN, g_bsumN);
    cudaGetSymbolAddress((void**)&p_Wt,    g_Wt);

    int* p_degNo = p_zb->degN;
    int* p_degNi = p_zb->degN + NNODES;
    int* p_degEo = p_zb->degE;
    int* p_degEi = p_zb->degE + NEDGES;
    int* p_cnt   = p_zb->cnt;
    float* p_pool = p_zb->pool;

    const float2* wtL[6];
    for (int l = 0; l < 6; l++) wtL[l] = (const float2*)p_Wt + (long)l * WT_LAYER;

    const int T = 256;
    const int gE = cdiv(NEDGES, 64), gN = cdiv(NNODES, 64);

    cudaStream_t s2;
    cudaStreamCreateWithFlags(&s2, cudaStreamNonBlocking);
    cudaEvent_t evRoot, evNode;
    cudaEventCreateWithFlags(&evRoot, cudaEventDisableTiming);
    cudaEventCreateWithFlags(&evNode, cudaEventDisableTiming);

    // ---- common prologue (main stream) ----
    k_zero_all<<<cdiv(sizeof(ZB) / 16, T), T>>>();
    k_wt<<<cdiv(6 * WT_LAYER, T), T>>>(gW, lgW, p_Wt);
    cudaEventRecord(evRoot, 0);

    // ---- node chain on s2 ----
    cudaStreamWaitEvent(s2, evRoot, 0);
    k_deg<<<cdiv(NEDGES, T), T, 0, s2>>>(src, dst, p_degNo, NNODES, NEDGES);
    k_scan1<<<cdiv(NNODES, SCAN_BS), SCAN_BS, 0, s2>>>(p_degNi, p_offN, p_bsumN, NNODES);
    k_scan2<<<1, SCAN_BS, 0, s2>>>(p_bsumN, cdiv(NNODES, SCAN_BS));
    k_scan3<<<cdiv(NNODES, T), T, 0, s2>>>(p_offN, p_bsumN, p_curN, NNODES);
    k_fill<<<cdiv(NEDGES, T), T, 0, s2>>>(src, dst, p_degNo, p_curN, p_csrN, NEDGES);
    k_conv<2, 0><<<gN, 128, 0, s2>>>(nullptr, nullptr, z, emb, nullptr, nullptr,
                                     p_degNi, p_offN, p_csrN,
                                     wtL[0], gb, p_hA, nullptr, nullptr, 0, NNODES);
    k_conv<0, 0><<<gN, 128, 0, s2>>>(p_hA, nullptr, nullptr, nullptr, nullptr, nullptr,
                                     p_degNi, p_offN, p_csrN,
                                     wtL[1], gb + HID, p_hB, nullptr, nullptr, 0, NNODES);
    k_conv<0, 1><<<gN, 128, 0, s2>>>(p_hB, nullptr, nullptr, nullptr, nullptr, nullptr,
                                     p_degNi, p_offN, p_csrN,
                                     wtL[2], gb + 2 * HID, nullptr, ng, p_pool, 0, NNODES);
    k_cnt<<<cdiv(NNODES, T), T, 0, s2>>>(ng, p_cnt, 0, NNODES);
    k_cnt<<<cdiv(NEDGES, T), T, 0, s2>>>(eg, p_cnt, NB, NEDGES);
    cudaEventRecord(evNode, s2);

    // ---- line chain on main stream ----
    k_deg<<<cdiv(NEDGES2, T), T>>>(lsrc, ldst, p_degEo, NEDGES, NEDGES2);
    k_scan1<<<cdiv(NEDGES, SCAN_BS), SCAN_BS>>>(p_degEi, p_offE, p_bsumE, NEDGES);
    k_scan2<<<1, SCAN_BS>>>(p_bsumE, cdiv(NEDGES, SCAN_BS));
    k_scan3<<<cdiv(NEDGES, T), T>>>(p_offE, p_bsumE, p_curE, NEDGES);
    k_fill<<<cdiv(NEDGES2, T), T>>>(lsrc, ldst, p_degEo, p_curE, p_csrE, NEDGES2);
    k_conv<1, 0><<<gE, 128>>>(nullptr, d, nullptr, nullptr, epw, epb,
                              p_degEi, p_offE, p_csrE,
                              wtL[3], lgb, p_eA, nullptr, nullptr, 0, NEDGES);
    k_conv<0, 0><<<gE, 128>>>(p_eA, nullptr, nullptr, nullptr, nullptr, nullptr,
                              p_degEi, p_offE, p_csrE,
                              wtL[4], lgb + HID, p_eB, nullptr, nullptr, 0, NEDGES);
    k_conv<0, 1><<<gE, 128>>>(p_eB, nullptr, nullptr, nullptr, nullptr, nullptr,
                              p_degEi, p_offE, p_csrE,
                              wtL[5], lgb + 2 * HID, nullptr, eg, p_pool, 128, NEDGES);

    // ---- join + readout ----
    cudaStreamWaitEvent(0, evNode, 0);
    k_readout<<<NB, 128>>>(p_pool, p_cnt, r1w, r1b, r2w, r2b, out);
}

// round 12
// speedup vs baseline: 2.0679x; 1.1598x over previous
#include <cuda_runtime.h>
#include <cuda_fp16.h>
#include <math.h>
#include <stdint.h>

// ---------------- problem constants ----------------
#define NNODES   100000
#define NEDGES   600000
#define NEDGES2  1500000
#define HID      128
#define HF4      32
#define NB       64
#define WT16_LAYER 4096   // entries per layer: 8 ks * 16 nf * 32 lanes (uint2 each)
#define SCAN_BS  1024

// ---------------- scratch ----------------
__device__ __half g_hA[(size_t)NNODES * HID];
__device__ __half g_hB[(size_t)NNODES * HID];
__device__ __half g_eA[(size_t)NEDGES * HID];
__device__ __half g_eB[(size_t)NEDGES * HID];

struct ZB {
    int degN[2 * NNODES];         // [out | in]
    int degE[2 * NEDGES];
    int cnt [2 * NB];
    float pool[NB * 256];
};
__device__ ZB  g_zb;
__device__ int g_offN[NNODES];
__device__ int g_curN[NNODES];
__device__ int g_offE[NEDGES];
__device__ int g_curE[NEDGES];
__device__ int2 g_csrN[NEDGES];    // (src, rsdeg_out(src) as float bits)
__device__ int2 g_csrE[NEDGES2];
__device__ int g_bsumE[SCAN_BS];
__device__ int g_bsumN[SCAN_BS];
__device__ uint2 g_Wt16[6 * WT16_LAYER];   // fp16 B-fragment table

// ---------------- helpers ----------------
__device__ __forceinline__ void red_add_v2(float* addr, float x, float y) {
    asm volatile("red.global.add.v2.f32 [%0], {%1,%2};"
                 :: "l"(addr), "f"(x), "f"(y) : "memory");
}
__device__ __forceinline__ void mma_f16(float& c0, float& c1, float& c2, float& c3,
                                        uint32_t a0, uint32_t a1, uint32_t a2, uint32_t a3,
                                        uint32_t b0, uint32_t b1) {
    asm volatile("mma.sync.aligned.m16n8k16.row.col.f32.f16.f16.f32 "
                 "{%0,%1,%2,%3}, {%4,%5,%6,%7}, {%8,%9}, {%0,%1,%2,%3};"
                 : "+f"(c0), "+f"(c1), "+f"(c2), "+f"(c3)
                 : "r"(a0), "r"(a1), "r"(a2), "r"(a3), "r"(b0), "r"(b1));
}
__device__ __forceinline__ float rsdeg_i(int d) {
    return rsqrtf(fmaxf((float)d, 1.f));
}

// ---------------- small kernels ----------------
__global__ void k_zero_all() {
    long n4 = sizeof(ZB) / 16;
    float4* p = (float4*)&g_zb;
    long i = (long)blockIdx.x * blockDim.x + threadIdx.x;
    if (i < n4) p[i] = make_float4(0.f, 0.f, 0.f, 0.f);
}

// fp16 B-fragment table for m16n8k16:
// Wt16[layer][ks][nf][lane] = { h2(W[k0+2t][n], W[k0+2t+1][n]),
//                               h2(W[k0+2t+8][n], W[k0+2t+9][n]) }
//   g=lane>>2, t=lane&3; n = nf*8+g; k0 = ks*16.
__global__ void k_wt16(const float* __restrict__ gW, const float* __restrict__ lgW,
                       uint2* __restrict__ Wt) {
    int idx = blockIdx.x * blockDim.x + threadIdx.x;
    if (idx >= 6 * WT16_LAYER) return;
    int layer = idx >> 12;
    int rem = idx & 4095;
    int ks = rem >> 9;
    int rem2 = rem & 511;
    int nf = rem2 >> 5, lane = rem2 & 31;
    int g = lane >> 2, t = lane & 3;
    int n = nf * 8 + g, k0 = ks * 16 + 2 * t;
    const float* W = (layer < 3) ? (gW + (long)layer * 16384)
                                 : (lgW + (long)(layer - 3) * 16384);
    __half2 b0 = __floats2half2_rn(__ldg(W + k0 * HID + n), __ldg(W + (k0 + 1) * HID + n));
    __half2 b1 = __floats2half2_rn(__ldg(W + (k0 + 8) * HID + n), __ldg(W + (k0 + 9) * HID + n));
    Wt[idx] = make_uint2(*(uint32_t*)&b0, *(uint32_t*)&b1);
}

__global__ void k_deg(const int* __restrict__ s, const int* __restrict__ t,
                      int* deg, int noff, int n) {
    int i = blockIdx.x * blockDim.x + threadIdx.x;
    if (i < n) {
        atomicAdd(deg + s[i], 1);
        atomicAdd(deg + noff + t[i], 1);
    }
}

__global__ void k_cnt(const int* __restrict__ seg, int* __restrict__ cnt,
                      int cntoff, int n) {
    __shared__ int h[NB];
    int t = threadIdx.x;
    if (t < NB) h[t] = 0;
    __syncthreads();
    int i = blockIdx.x * blockDim.x + t;
    if (i < n) atomicAdd(h + seg[i], 1);
    __syncthreads();
    if (t < NB && h[t]) atomicAdd(cnt + cntoff + t, h[t]);
}

__global__ void k_scan1(const int* __restrict__ deg, int* __restrict__ off,
                        int* __restrict__ bsum, int n) {
    __shared__ int sh[SCAN_BS];
    int t = threadIdx.x;
    int i = blockIdx.x * SCAN_BS + t;
    int v = (i < n) ? deg[i] : 0;
    sh[t] = v;
    __syncthreads();
    for (int s = 1; s < SCAN_BS; s <<= 1) {
        int add = (t >= s) ? sh[t - s] : 0;
        __syncthreads();
        sh[t] += add;
        __syncthreads();
    }
    if (i < n) off[i] = sh[t] - v;
    if (t == SCAN_BS - 1) bsum[blockIdx.x] = sh[t];
}
__global__ void k_scan2(int* bsum, int nb) {
    __shared__ int sh[SCAN_BS];
    int t = threadIdx.x;
    int v = (t < nb) ? bsum[t] : 0;
    sh[t] = v;
    __syncthreads();
    for (int s = 1; s < SCAN_BS; s <<= 1) {
        int add = (t >= s) ? sh[t - s] : 0;
        __syncthreads();
        sh[t] += add;
        __syncthreads();
    }
    if (t < nb) bsum[t] = sh[t] - v;
}
__global__ void k_scan3(int* __restrict__ off, const int* __restrict__ bsum,
                        int* __restrict__ cur, int n) {
    int i = blockIdx.x * blockDim.x + threadIdx.x;
    if (i < n) {
        int o = off[i] + bsum[i >> 10];
        off[i] = o;
        cur[i] = o;
    }
}
__global__ void k_fill(const int* __restrict__ s, const int* __restrict__ t,
                       const int* __restrict__ dego,
                       int* __restrict__ cur, int2* __restrict__ csr, int n) {
    int i = blockIdx.x * blockDim.x + threadIdx.x;
    if (i < n) {
        int si = s[i];
        float sc = rsdeg_i(__ldg(dego + si));
        int p = atomicAdd(cur + t[i], 1);
        csr[p] = make_int2(si, __float_as_int(sc));
    }
}

// ---------------- fused CSR-gather + fp16 tensor-core GEMM -----------------
// MODE 0: f = feat16[s];  MODE 1: f = d[s]*ep_w + ep_b;  MODE 2: f = emb[z[s]]
// EPI  0: store rows fp16;  EPI 1: red.add into pool (fp32)
// gather source and 'out16' must be distinct buffers (ping-pong).
#define XH_STRIDE 136   // halfs per A-tile row (128 + 8 pad)
template<int MODE, int EPI>
__global__ void __launch_bounds__(128)
k_conv(const __half* __restrict__ feat16, const float* __restrict__ dvec,
       const int* __restrict__ z, const float* __restrict__ emb,
       const float* __restrict__ epw, const float* __restrict__ epb,
       const int* __restrict__ degi,
       const int* __restrict__ off, const int2* __restrict__ csr,
       const uint2* __restrict__ Wt, const float* __restrict__ bias,
       __half* __restrict__ out16, const int* __restrict__ seg,
       float* __restrict__ pool, int coloff, int rows) {
    __shared__ __align__(16) __half Xs[64 * XH_STRIDE];
    int tid = threadIdx.x;
    int warp = tid >> 5, lane = tid & 31;
    int g = lane >> 2, tig = lane & 3;
    long r0 = (long)blockIdx.x * 64;

    // ---- phase 1: gather A-tile (warp per row, 16 rows per warp) ----
    float4 wv, bv;
    if (MODE == 1) { wv = ((const float4*)epw)[lane]; bv = ((const float4*)epb)[lane]; }
    for (int rl = warp; rl < 64; rl += 4) {
        long r = r0 + rl;
        float4 acc = make_float4(0.f, 0.f, 0.f, 0.f);
        float si = 0.f;
        if (r < rows) {
            int beg = __ldg(off + r), dg = __ldg(degi + r);
            for (int j = beg; j < beg + dg; j++) {
                int2 en = __ldg(csr + j);
                int s = en.x;
                float sc = __int_as_float(en.y);
                if (MODE == 0) {
                    uint2 raw = __ldg((const uint2*)feat16 + (long)s * 32 + lane);
                    float2 f0 = __half22float2(*(__half2*)&raw.x);
                    float2 f1 = __half22float2(*(__half2*)&raw.y);
                    acc.x += f0.x * sc; acc.y += f0.y * sc;
                    acc.z += f1.x * sc; acc.w += f1.y * sc;
                } else if (MODE == 1) {
                    float dv = __ldg(dvec + s) * sc;
                    acc.x += dv * wv.x + bv.x * sc;
                    acc.y += dv * wv.y + bv.y * sc;
                    acc.z += dv * wv.z + bv.z * sc;
                    acc.w += dv * wv.w + bv.w * sc;
                } else {
                    int zi = __ldg(z + s);
                    float4 v = __ldg((const float4*)emb + (long)zi * HF4 + lane);
                    acc.x += v.x * sc; acc.y += v.y * sc;
                    acc.z += v.z * sc; acc.w += v.w * sc;
                }
            }
            si = rsdeg_i(dg);
        }
        __half2 h0 = __floats2half2_rn(acc.x * si, acc.y * si);
        __half2 h1 = __floats2half2_rn(acc.z * si, acc.w * si);
        *(uint2*)(Xs + rl * XH_STRIDE + lane * 4) =
            make_uint2(*(uint32_t*)&h0, *(uint32_t*)&h1);
    }
    __syncthreads();

    // ---- phase 2: 64x128 @ 128x128 fp16 MMA (m16n8k16, fp32 accum) ----
    float acc[16][4];
#pragma unroll
    for (int nf = 0; nf < 16; nf++)
#pragma unroll
        for (int j = 0; j < 4; j++) acc[nf][j] = 0.f;

    const __half* xa = Xs + (warp * 16 + g) * XH_STRIDE + 2 * tig;
    const uint2* wt = Wt + lane;
#pragma unroll
    for (int ks = 0; ks < 8; ks++) {
        int k0 = ks * 16;
        uint32_t a0 = *(const uint32_t*)(xa + k0);
        uint32_t a1 = *(const uint32_t*)(xa + 8 * XH_STRIDE + k0);
        uint32_t a2 = *(const uint32_t*)(xa + k0 + 8);
        uint32_t a3 = *(const uint32_t*)(xa + 8 * XH_STRIDE + k0 + 8);
#pragma unroll
        for (int nf = 0; nf < 16; nf++) {
            uint2 b = __ldg(wt + (ks * 16 + nf) * 32);
            mma_f16(acc[nf][0], acc[nf][1], acc[nf][2], acc[nf][3],
                    a0, a1, a2, a3, b.x, b.y);
        }
    }

    long row0 = r0 + warp * 16 + g;
    long row1 = row0 + 8;
    int seg0 = 0, seg1 = 0;
    if (EPI == 1) {
        if (row0 < rows) seg0 = __ldg(seg + row0);
        if (row1 < rows) seg1 = __ldg(seg + row1);
    }
#pragma unroll
    for (int nf = 0; nf < 16; nf++) {
        int n0 = nf * 8 + 2 * tig;
        float b0 = __ldg(bias + n0), b1 = __ldg(bias + n0 + 1);
        if (row0 < rows) {
            float ox = fmaxf(acc[nf][0] + b0, 0.f);
            float oy = fmaxf(acc[nf][1] + b1, 0.f);
            if (EPI == 0) *(__half2*)(out16 + row0 * HID + n0) = __floats2half2_rn(ox, oy);
            else red_add_v2(pool + (long)seg0 * 256 + coloff + n0, ox, oy);
        }
        if (row1 < rows) {
            float ox = fmaxf(acc[nf][2] + b0, 0.f);
            float oy = fmaxf(acc[nf][3] + b1, 0.f);
            if (EPI == 0) *(__half2*)(out16 + row1 * HID + n0) = __floats2half2_rn(ox, oy);
            else red_add_v2(pool + (long)seg1 * 256 + coloff + n0, ox, oy);
        }
    }
}

// final MLP
__global__ void k_readout(const float* __restrict__ pool, const int* __restrict__ cnt,
                          const float* __restrict__ r1w, const float* __restrict__ r1b,
                          const float* __restrict__ r2w, const float* __restrict__ r2b,
                          float* __restrict__ out) {
    __shared__ float x[256];
    __shared__ float redbuf[128];
    int g = blockIdx.x, tid = threadIdx.x;
    float cn = fmaxf((float)cnt[g], 1.f);
    float ce = fmaxf((float)cnt[NB + g], 1.f);
    x[tid]       = pool[g * 256 + tid] / cn;
    x[128 + tid] = pool[g * 256 + 128 + tid] / ce;
    __syncthreads();
    float a = r1b[tid];
#pragma unroll 8
    for (int k = 0; k < 256; k++) a += x[k] * r1w[k * 128 + tid];
    float sig = 1.f / (1.f + expf(-a));
    float p = a * sig * r2w[tid];
    redbuf[tid] = p;
    __syncthreads();
    for (int s = 64; s > 0; s >>= 1) {
        if (tid < s) redbuf[tid] += redbuf[tid + s];
        __syncthreads();
    }
    if (tid == 0) out[g] = redbuf[0] + r2b[0];
}

// ---------------- launch ----------------
static inline int cdiv(long a, long b) { return (int)((a + b - 1) / b); }

extern "C" void kernel_launch(void* const* d_in, const int* in_sizes, int n_in,
                              void* d_out, int out_size) {
    const int*   z    = (const int*)  d_in[0];
    const float* d    = (const float*)d_in[1];
    const int*   src  = (const int*)  d_in[2];
    const int*   dst  = (const int*)  d_in[3];
    const int*   lsrc = (const int*)  d_in[4];
    const int*   ldst = (const int*)  d_in[5];
    const int*   ng   = (const int*)  d_in[6];
    const int*   eg   = (const int*)  d_in[7];
    const float* emb  = (const float*)d_in[8];
    const float* epw  = (const float*)d_in[9];
    const float* epb  = (const float*)d_in[10];
    const float* gW   = (const float*)d_in[11];
    const float* gb   = (const float*)d_in[12];
    const float* lgW  = (const float*)d_in[13];
    const float* lgb  = (const float*)d_in[14];
    const float* r1w  = (const float*)d_in[15];
    const float* r1b  = (const float*)d_in[16];
    const float* r2w  = (const float*)d_in[17];
    const float* r2b  = (const float*)d_in[18];
    float* out = (float*)d_out;

    __half *p_hA, *p_hB, *p_eA, *p_eB;
    uint2 *p_Wt16;
    int *p_offN, *p_curN, *p_offE, *p_curE, *p_bsumE, *p_bsumN;
    int2 *p_csrN, *p_csrE;
    ZB* p_zb;
    cudaGetSymbolAddress((void**)&p_hA,    g_hA);
    cudaGetSymbolAddress((void**)&p_hB,    g_hB);
    cudaGetSymbolAddress((void**)&p_eA,    g_eA);
    cudaGetSymbolAddress((void**)&p_eB,    g_eB);
    cudaGetSymbolAddress((void**)&p_zb,    g_zb);
    cudaGetSymbolAddress((void**)&p_offN,  g_offN);
    cudaGetSymbolAddress((void**)&p_curN,  g_curN);
    cudaGetSymbolAddress((void**)&p_offE,  g_offE);
    cudaGetSymbolAddress((void**)&p_curE,  g_curE);
    cudaGetSymbolAddress((void**)&p_csrN,  g_csrN);
    cudaGetSymbolAddress((void**)&p_csrE,  g_csrE);
    cudaGetSymbolAddress((void**)&p_bsumE, g_bsumE);
    cudaGetSymbolAddress((void**)&p_bsumN, g_bsumN);
    cudaGetSymbolAddress((void**)&p_Wt16,  g_Wt16);

    int* p_degNo = p_zb->degN;
    int* p_degNi = p_zb->degN + NNODES;
    int* p_degEo = p_zb->degE;
    int* p_degEi = p_zb->degE + NEDGES;
    int* p_cnt   = p_zb->cnt;
    float* p_pool = p_zb->pool;

    const uint2* wtL[6];
    for (int l = 0; l < 6; l++) wtL[l] = p_Wt16 + (long)l * WT16_LAYER;

    const int T = 256;
    const int gE = cdiv(NEDGES, 64), gN = cdiv(NNODES, 64);

    cudaStream_t s2;
    cudaStreamCreateWithFlags(&s2, cudaStreamNonBlocking);
    cudaEvent_t evRoot, evNode;
    cudaEventCreateWithFlags(&evRoot, cudaEventDisableTiming);
    cudaEventCreateWithFlags(&evNode, cudaEventDisableTiming);

    // ---- common prologue (main stream) ----
    k_zero_all<<<cdiv(sizeof(ZB) / 16, T), T>>>();
    k_wt16<<<cdiv(6 * WT16_LAYER, T), T>>>(gW, lgW, p_Wt16);
    cudaEventRecord(evRoot, 0);

    // ---- node chain on s2 ----
    cudaStreamWaitEvent(s2, evRoot, 0);
    k_deg<<<cdiv(NEDGES, T), T, 0, s2>>>(src, dst, p_degNo, NNODES, NEDGES);
    k_scan1<<<cdiv(NNODES, SCAN_BS), SCAN_BS, 0, s2>>>(p_degNi, p_offN, p_bsumN, NNODES);
    k_scan2<<<1, SCAN_BS, 0, s2>>>(p_bsumN, cdiv(NNODES, SCAN_BS));
    k_scan3<<<cdiv(NNODES, T), T, 0, s2>>>(p_offN, p_bsumN, p_curN, NNODES);
    k_fill<<<cdiv(NEDGES, T), T, 0, s2>>>(src, dst, p_degNo, p_curN, p_csrN, NEDGES);
    k_conv<2, 0><<<gN, 128, 0, s2>>>(nullptr, nullptr, z, emb, nullptr, nullptr,
                                     p_degNi, p_offN, p_csrN,
                                     wtL[0], gb, p_hA, nullptr, nullptr, 0, NNODES);
    k_conv<0, 0><<<gN, 128, 0, s2>>>(p_hA, nullptr, nullptr, nullptr, nullptr, nullptr,
                                     p_degNi, p_offN, p_csrN,
                                     wtL[1], gb + HID, p_hB, nullptr, nullptr, 0, NNODES);
    k_conv<0, 1><<<gN, 128, 0, s2>>>(p_hB, nullptr, nullptr, nullptr, nullptr, nullptr,
                                     p_degNi, p_offN, p_csrN,
                                     wtL[2], gb + 2 * HID, nullptr, ng, p_pool, 0, NNODES);
    k_cnt<<<cdiv(NNODES, T), T, 0, s2>>>(ng, p_cnt, 0, NNODES);
    k_cnt<<<cdiv(NEDGES, T), T, 0, s2>>>(eg, p_cnt, NB, NEDGES);
    cudaEventRecord(evNode, s2);

    // ---- line chain on main stream ----
    k_deg<<<cdiv(NEDGES2, T), T>>>(lsrc, ldst, p_degEo, NEDGES, NEDGES2);
    k_scan1<<<cdiv(NEDGES, SCAN_BS), SCAN_BS>>>(p_degEi, p_offE, p_bsumE, NEDGES);
    k_scan2<<<1, SCAN_BS>>>(p_bsumE, cdiv(NEDGES, SCAN_BS));
    k_scan3<<<cdiv(NEDGES, T), T>>>(p_offE, p_bsumE, p_curE, NEDGES);
    k_fill<<<cdiv(NEDGES2, T), T>>>(lsrc, ldst, p_degEo, p_curE, p_csrE, NEDGES2);
    k_conv<1, 0><<<gE, 128>>>(nullptr, d, nullptr, nullptr, epw, epb,
                              p_degEi, p_offE, p_csrE,
                              wtL[3], lgb, p_eA, nullptr, nullptr, 0, NEDGES);
    k_conv<0, 0><<<gE, 128>>>(p_eA, nullptr, nullptr, nullptr, nullptr, nullptr,
                              p_degEi, p_offE, p_csrE,
                              wtL[4], lgb + HID, p_eB, nullptr, nullptr, 0, NEDGES);
    k_conv<0, 1><<<gE, 128>>>(p_eB, nullptr, nullptr, nullptr, nullptr, nullptr,
                              p_degEi, p_offE, p_csrE,
                              wtL[5], lgb + 2 * HID, nullptr, eg, p_pool, 128, NEDGES);

    // ---- join + readout ----
    cudaStreamWaitEvent(0, evNode, 0);
    k_readout<<<NB, 128>>>(p_pool, p_cnt, r1w, r1b, r2w, r2b, out);
}

// round 13
// speedup vs baseline: 2.1271x; 1.0286x over previous
#include <cuda_runtime.h>
#include <cuda_fp16.h>
#include <math.h>
#include <stdint.h>

// ---------------- problem constants ----------------
#define NNODES   100000
#define NEDGES   600000
#define NEDGES2  1500000
#define HID      128
#define HF4      32
#define NB       64
#define WT16_LAYER 4096   // entries per layer: 8 ks * 16 nf * 32 lanes (uint2)
#define SCAN_BS  1024

// ---------------- scratch ----------------
__device__ __half g_hA[(size_t)NNODES * HID];
__device__ __half g_hB[(size_t)NNODES * HID];
__device__ __half g_eA[(size_t)NEDGES * HID];
__device__ __half g_eB[(size_t)NEDGES * HID];

struct ZB {
    int degN[2 * NNODES];         // [out | in]
    int degE[2 * NEDGES];
    int cnt [2 * NB];
    float pool[NB * 256];
};
__device__ ZB  g_zb;
__device__ int g_offN[NNODES];
__device__ int g_curN[NNODES];
__device__ int g_offE[NEDGES];
__device__ int g_curE[NEDGES];
__device__ int2 g_csrN[NEDGES];    // (src, rsdeg_out(src) as float bits)
__device__ int2 g_csrE[NEDGES2];
__device__ int g_bsumE[SCAN_BS];
__device__ int g_bsumN[SCAN_BS];
__device__ uint2 g_Wt16[6 * WT16_LAYER];

// ---------------- helpers ----------------
__device__ __forceinline__ void red_add_v2(float* addr, float x, float y) {
    asm volatile("red.global.add.v2.f32 [%0], {%1,%2};"
                 :: "l"(addr), "f"(x), "f"(y) : "memory");
}
__device__ __forceinline__ void mma_f16(float& c0, float& c1, float& c2, float& c3,
                                        uint32_t a0, uint32_t a1, uint32_t a2, uint32_t a3,
                                        uint32_t b0, uint32_t b1) {
    asm volatile("mma.sync.aligned.m16n8k16.row.col.f32.f16.f16.f32 "
                 "{%0,%1,%2,%3}, {%4,%5,%6,%7}, {%8,%9}, {%0,%1,%2,%3};"
                 : "+f"(c0), "+f"(c1), "+f"(c2), "+f"(c3)
                 : "r"(a0), "r"(a1), "r"(a2), "r"(a3), "r"(b0), "r"(b1));
}
__device__ __forceinline__ float rsdeg_i(int d) {
    return rsqrtf(fmaxf((float)d, 1.f));
}

// ---------------- small kernels ----------------
__global__ void k_zero_all() {
    long n4 = sizeof(ZB) / 16;
    float4* p = (float4*)&g_zb;
    long i = (long)blockIdx.x * blockDim.x + threadIdx.x;
    if (i < n4) p[i] = make_float4(0.f, 0.f, 0.f, 0.f);
}

__global__ void k_wt16(const float* __restrict__ gW, const float* __restrict__ lgW,
                       uint2* __restrict__ Wt) {
    int idx = blockIdx.x * blockDim.x + threadIdx.x;
    if (idx >= 6 * WT16_LAYER) return;
    int layer = idx >> 12;
    int rem = idx & 4095;
    int ks = rem >> 9;
    int rem2 = rem & 511;
    int nf = rem2 >> 5, lane = rem2 & 31;
    int g = lane >> 2, t = lane & 3;
    int n = nf * 8 + g, k0 = ks * 16 + 2 * t;
    const float* W = (layer < 3) ? (gW + (long)layer * 16384)
                                 : (lgW + (long)(layer - 3) * 16384);
    __half2 b0 = __floats2half2_rn(__ldg(W + k0 * HID + n), __ldg(W + (k0 + 1) * HID + n));
    __half2 b1 = __floats2half2_rn(__ldg(W + (k0 + 8) * HID + n), __ldg(W + (k0 + 9) * HID + n));
    Wt[idx] = make_uint2(*(uint32_t*)&b0, *(uint32_t*)&b1);
}

__global__ void k_deg(const int* __restrict__ s, const int* __restrict__ t,
                      int* deg, int noff, int n) {
    int i = blockIdx.x * blockDim.x + threadIdx.x;
    if (i < n) {
        atomicAdd(deg + s[i], 1);
        atomicAdd(deg + noff + t[i], 1);
    }
}

__global__ void k_cnt(const int* __restrict__ seg, int* __restrict__ cnt,
                      int cntoff, int n) {
    __shared__ int h[NB];
    int t = threadIdx.x;
    if (t < NB) h[t] = 0;
    __syncthreads();
    int i = blockIdx.x * blockDim.x + t;
    if (i < n) atomicAdd(h + seg[i], 1);
    __syncthreads();
    if (t < NB && h[t]) atomicAdd(cnt + cntoff + t, h[t]);
}

__global__ void k_scan1(const int* __restrict__ deg, int* __restrict__ off,
                        int* __restrict__ bsum, int n) {
    __shared__ int sh[SCAN_BS];
    int t = threadIdx.x;
    int i = blockIdx.x * SCAN_BS + t;
    int v = (i < n) ? deg[i] : 0;
    sh[t] = v;
    __syncthreads();
    for (int s = 1; s < SCAN_BS; s <<= 1) {
        int add = (t >= s) ? sh[t - s] : 0;
        __syncthreads();
        sh[t] += add;
        __syncthreads();
    }
    if (i < n) off[i] = sh[t] - v;
    if (t == SCAN_BS - 1) bsum[blockIdx.x] = sh[t];
}
__global__ void k_scan2(int* bsum, int nb) {
    __shared__ int sh[SCAN_BS];
    int t = threadIdx.x;
    int v = (t < nb) ? bsum[t] : 0;
    sh[t] = v;
    __syncthreads();
    for (int s = 1; s < SCAN_BS; s <<= 1) {
        int add = (t >= s) ? sh[t - s] : 0;
        __syncthreads();
        sh[t] += add;
        __syncthreads();
    }
    if (t < nb) bsum[t] = sh[t] - v;
}
__global__ void k_scan3(int* __restrict__ off, const int* __restrict__ bsum,
                        int* __restrict__ cur, int n) {
    int i = blockIdx.x * blockDim.x + threadIdx.x;
    if (i < n) {
        int o = off[i] + bsum[i >> 10];
        off[i] = o;
        cur[i] = o;
    }
}
__global__ void k_fill(const int* __restrict__ s, const int* __restrict__ t,
                       const int* __restrict__ dego,
                       int* __restrict__ cur, int2* __restrict__ csr, int n) {
    int i = blockIdx.x * blockDim.x + threadIdx.x;
    if (i < n) {
        int si = s[i];
        float sc = rsdeg_i(__ldg(dego + si));
        int p = atomicAdd(cur + t[i], 1);
        csr[p] = make_int2(si, __float_as_int(sc));
    }
}

// ---------------- fused CSR-gather + fp16 tensor-core GEMM -----------------
// Phase 1 gathers rows in PAIRS per warp (two interleaved edge loops, dual
// accumulators): serial chain per pair = max(dgA,dgB) instead of dgA+dgB.
// MODE 0: f = feat16[s];  MODE 1: f = d[s]*ep_w + ep_b;  MODE 2: f = emb[z[s]]
// EPI  0: store rows fp16;  EPI 1: red.add into pool (fp32)
#define XH_STRIDE 136   // halfs per A-tile row (128 + 8 pad)
template<int MODE, int EPI>
__global__ void __launch_bounds__(128)
k_conv(const __half* __restrict__ feat16, const float* __restrict__ dvec,
       const int* __restrict__ z, const float* __restrict__ emb,
       const float* __restrict__ epw, const float* __restrict__ epb,
       const int* __restrict__ degi,
       const int* __restrict__ off, const int2* __restrict__ csr,
       const uint2* __restrict__ Wt, const float* __restrict__ bias,
       __half* __restrict__ out16, const int* __restrict__ seg,
       float* __restrict__ pool, int coloff, int rows) {
    __shared__ __align__(16) __half Xs[64 * XH_STRIDE];
    int tid = threadIdx.x;
    int warp = tid >> 5, lane = tid & 31;
    int g = lane >> 2, tig = lane & 3;
    long r0 = (long)blockIdx.x * 64;

    // ---- phase 1: paired-row gather (8 pairs per warp) ----
    float4 wv, bv;
    if (MODE == 1) { wv = ((const float4*)epw)[lane]; bv = ((const float4*)epb)[lane]; }
    for (int rl = warp; rl < 64; rl += 8) {
        int rlA = rl, rlB = rl + 4;
        long rA = r0 + rlA, rB = r0 + rlB;
        float4 accA = make_float4(0.f, 0.f, 0.f, 0.f);
        float4 accB = make_float4(0.f, 0.f, 0.f, 0.f);
        int begA = 0, dgA = 0, begB = 0, dgB = 0;
        float siA = 0.f, siB = 0.f;
        if (rA < rows) { begA = __ldg(off + rA); dgA = __ldg(degi + rA); siA = rsdeg_i(dgA); }
        if (rB < rows) { begB = __ldg(off + rB); dgB = __ldg(degi + rB); siB = rsdeg_i(dgB); }
        int m = dgA > dgB ? dgA : dgB;
        for (int j = 0; j < m; j++) {
            bool pA = j < dgA, pB = j < dgB;
            int2 eA, eB;
            if (pA) eA = __ldg(csr + begA + j);
            if (pB) eB = __ldg(csr + begB + j);
            if (pA) {
                float sc = __int_as_float(eA.y);
                if (MODE == 0) {
                    uint2 raw = __ldg((const uint2*)feat16 + (long)eA.x * 32 + lane);
                    float2 f0 = __half22float2(*(__half2*)&raw.x);
                    float2 f1 = __half22float2(*(__half2*)&raw.y);
                    accA.x += f0.x * sc; accA.y += f0.y * sc;
                    accA.z += f1.x * sc; accA.w += f1.y * sc;
                } else if (MODE == 1) {
                    float dv = __ldg(dvec + eA.x) * sc;
                    accA.x += dv * wv.x + bv.x * sc;
                    accA.y += dv * wv.y + bv.y * sc;
                    accA.z += dv * wv.z + bv.z * sc;
                    accA.w += dv * wv.w + bv.w * sc;
                } else {
                    int zi = __ldg(z + eA.x);
                    float4 v = __ldg((const float4*)emb + (long)zi * HF4 + lane);
                    accA.x += v.x * sc; accA.y += v.y * sc;
                    accA.z += v.z * sc; accA.w += v.w * sc;
                }
            }
            if (pB) {
                float sc = __int_as_float(eB.y);
                if (MODE == 0) {
                    uint2 raw = __ldg((const uint2*)feat16 + (long)eB.x * 32 + lane);
                    float2 f0 = __half22float2(*(__half2*)&raw.x);
                    float2 f1 = __half22float2(*(__half2*)&raw.y);
                    accB.x += f0.x * sc; accB.y += f0.y * sc;
                    accB.z += f1.x * sc; accB.w += f1.y * sc;
                } else if (MODE == 1) {
                    float dv = __ldg(dvec + eB.x) * sc;
                    accB.x += dv * wv.x + bv.x * sc;
                    accB.y += dv * wv.y + bv.y * sc;
                    accB.z += dv * wv.z + bv.z * sc;
                    accB.w += dv * wv.w + bv.w * sc;
                } else {
                    int zi = __ldg(z + eB.x);
                    float4 v = __ldg((const float4*)emb + (long)zi * HF4 + lane);
                    accB.x += v.x * sc; accB.y += v.y * sc;
                    accB.z += v.z * sc; accB.w += v.w * sc;
                }
            }
        }
        __half2 a0 = __floats2half2_rn(accA.x * siA, accA.y * siA);
        __half2 a1 = __floats2half2_rn(accA.z * siA, accA.w * siA);
        *(uint2*)(Xs + rlA * XH_STRIDE + lane * 4) =
            make_uint2(*(uint32_t*)&a0, *(uint32_t*)&a1);
        __half2 b0 = __floats2half2_rn(accB.x * siB, accB.y * siB);
        __half2 b1 = __floats2half2_rn(accB.z * siB, accB.w * siB);
        *(uint2*)(Xs + rlB * XH_STRIDE + lane * 4) =
            make_uint2(*(uint32_t*)&b0, *(uint32_t*)&b1);
    }
    __syncthreads();

    // ---- phase 2: 64x128 @ 128x128 fp16 MMA (m16n8k16, fp32 accum) ----
    float acc[16][4];
#pragma unroll
    for (int nf = 0; nf < 16; nf++)
#pragma unroll
        for (int j = 0; j < 4; j++) acc[nf][j] = 0.f;

    const __half* xa = Xs + (warp * 16 + g) * XH_STRIDE + 2 * tig;
    const uint2* wt = Wt + lane;
#pragma unroll
    for (int ks = 0; ks < 8; ks++) {
        int k0 = ks * 16;
        uint32_t a0 = *(const uint32_t*)(xa + k0);
        uint32_t a1 = *(const uint32_t*)(xa + 8 * XH_STRIDE + k0);
        uint32_t a2 = *(const uint32_t*)(xa + k0 + 8);
        uint32_t a3 = *(const uint32_t*)(xa + 8 * XH_STRIDE + k0 + 8);
#pragma unroll
        for (int nf = 0; nf < 16; nf++) {
            uint2 b = __ldg(wt + (ks * 16 + nf) * 32);
            mma_f16(acc[nf][0], acc[nf][1], acc[nf][2], acc[nf][3],
                    a0, a1, a2, a3, b.x, b.y);
        }
    }

    long row0 = r0 + warp * 16 + g;
    long row1 = row0 + 8;
    int seg0 = 0, seg1 = 0;
    if (EPI == 1) {
        if (row0 < rows) seg0 = __ldg(seg + row0);
        if (row1 < rows) seg1 = __ldg(seg + row1);
    }
#pragma unroll
    for (int nf = 0; nf < 16; nf++) {
        int n0 = nf * 8 + 2 * tig;
        float b0 = __ldg(bias + n0), b1 = __ldg(bias + n0 + 1);
        if (row0 < rows) {
            float ox = fmaxf(acc[nf][0] + b0, 0.f);
            float oy = fmaxf(acc[nf][1] + b1, 0.f);
            if (EPI == 0) *(__half2*)(out16 + row0 * HID + n0) = __floats2half2_rn(ox, oy);
            else red_add_v2(pool + (long)seg0 * 256 + coloff + n0, ox, oy);
        }
        if (row1 < rows) {
            float ox = fmaxf(acc[nf][2] + b0, 0.f);
            float oy = fmaxf(acc[nf][3] + b1, 0.f);
            if (EPI == 0) *(__half2*)(out16 + row1 * HID + n0) = __floats2half2_rn(ox, oy);
            else red_add_v2(pool + (long)seg1 * 256 + coloff + n0, ox, oy);
        }
    }
}

// final MLP
__global__ void k_readout(const float* __restrict__ pool, const int* __restrict__ cnt,
                          const float* __restrict__ r1w, const float* __restrict__ r1b,
                          const float* __restrict__ r2w, const float* __restrict__ r2b,
                          float* __restrict__ out) {
    __shared__ float x[256];
    __shared__ float redbuf[128];
    int g = blockIdx.x, tid = threadIdx.x;
    float cn = fmaxf((float)cnt[g], 1.f);
    float ce = fmaxf((float)cnt[NB + g], 1.f);
    x[tid]       = pool[g * 256 + tid] / cn;
    x[128 + tid] = pool[g * 256 + 128 + tid] / ce;
    __syncthreads();
    float a = r1b[tid];
#pragma unroll 8
    for (int k = 0; k < 256; k++) a += x[k] * r1w[k * 128 + tid];
    float sig = 1.f / (1.f + expf(-a));
    float p = a * sig * r2w[tid];
    redbuf[tid] = p;
    __syncthreads();
    for (int s = 64; s > 0; s >>= 1) {
        if (tid < s) redbuf[tid] += redbuf[tid + s];
        __syncthreads();
    }
    if (tid == 0) out[g] = redbuf[0] + r2b[0];
}

// ---------------- launch ----------------
static inline int cdiv(long a, long b) { return (int)((a + b - 1) / b); }

extern "C" void kernel_launch(void* const* d_in, const int* in_sizes, int n_in,
                              void* d_out, int out_size) {
    const int*   z    = (const int*)  d_in[0];
    const float* d    = (const float*)d_in[1];
    const int*   src  = (const int*)  d_in[2];
    const int*   dst  = (const int*)  d_in[3];
    const int*   lsrc = (const int*)  d_in[4];
    const int*   ldst = (const int*)  d_in[5];
    const int*   ng   = (const int*)  d_in[6];
    const int*   eg   = (const int*)  d_in[7];
    const float* emb  = (const float*)d_in[8];
    const float* epw  = (const float*)d_in[9];
    const float* epb  = (const float*)d_in[10];
    const float* gW   = (const float*)d_in[11];
    const float* gb   = (const float*)d_in[12];
    const float* lgW  = (const float*)d_in[13];
    const float* lgb  = (const float*)d_in[14];
    const float* r1w  = (const float*)d_in[15];
    const float* r1b  = (const float*)d_in[16];
    const float* r2w  = (const float*)d_in[17];
    const float* r2b  = (const float*)d_in[18];
    float* out = (float*)d_out;

    __half *p_hA, *p_hB, *p_eA, *p_eB;
    uint2 *p_Wt16;
    int *p_offN, *p_curN, *p_offE, *p_curE, *p_bsumE, *p_bsumN;
    int2 *p_csrN, *p_csrE;
    ZB* p_zb;
    cudaGetSymbolAddress((void**)&p_hA,    g_hA);
    cudaGetSymbolAddress((void**)&p_hB,    g_hB);
    cudaGetSymbolAddress((void**)&p_eA,    g_eA);
    cudaGetSymbolAddress((void**)&p_eB,    g_eB);
    cudaGetSymbolAddress((void**)&p_zb,    g_zb);
    cudaGetSymbolAddress((void**)&p_offN,  g_offN);
    cudaGetSymbolAddress((void**)&p_curN,  g_curN);
    cudaGetSymbolAddress((void**)&p_offE,  g_offE);
    cudaGetSymbolAddress((void**)&p_curE,  g_curE);
    cudaGetSymbolAddress((void**)&p_csrN,  g_csrN);
    cudaGetSymbolAddress((void**)&p_csrE,  g_csrE);
    cudaGetSymbolAddress((void**)&p_bsumE, g_bsumE);
    cudaGetSymbolAddress((void**)&p_bsumN, g_bsumN);
    cudaGetSymbolAddress((void**)&p_Wt16,  g_Wt16);

    int* p_degNo = p_zb->degN;
    int* p_degNi = p_zb->degN + NNODES;
    int* p_degEo = p_zb->degE;
    int* p_degEi = p_zb->degE + NEDGES;
    int* p_cnt   = p_zb->cnt;
    float* p_pool = p_zb->pool;

    const uint2* wtL[6];
    for (int l = 0; l < 6; l++) wtL[l] = p_Wt16 + (long)l * WT16_LAYER;

    const int T = 256;
    const int gE = cdiv(NEDGES, 64), gN = cdiv(NNODES, 64);

    cudaStream_t s2;
    cudaStreamCreateWithFlags(&s2, cudaStreamNonBlocking);
    cudaEvent_t evRoot, evNode;
    cudaEventCreateWithFlags(&evRoot, cudaEventDisableTiming);
    cudaEventCreateWithFlags(&evNode, cudaEventDisableTiming);

    // ---- common prologue (main stream) ----
    k_zero_all<<<cdiv(sizeof(ZB) / 16, T), T>>>();
    k_wt16<<<cdiv(6 * WT16_LAYER, T), T>>>(gW, lgW, p_Wt16);
    cudaEventRecord(evRoot, 0);

    // ---- node chain on s2 ----
    cudaStreamWaitEvent(s2, evRoot, 0);
    k_deg<<<cdiv(NEDGES, T), T, 0, s2>>>(src, dst, p_degNo, NNODES, NEDGES);
    k_scan1<<<cdiv(NNODES, SCAN_BS), SCAN_BS, 0, s2>>>(p_degNi, p_offN, p_bsumN, NNODES);
    k_scan2<<<1, SCAN_BS, 0, s2>>>(p_bsumN, cdiv(NNODES, SCAN_BS));
    k_scan3<<<cdiv(NNODES, T), T, 0, s2>>>(p_offN, p_bsumN, p_curN, NNODES);
    k_fill<<<cdiv(NEDGES, T), T, 0, s2>>>(src, dst, p_degNo, p_curN, p_csrN, NEDGES);
    k_conv<2, 0><<<gN, 128, 0, s2>>>(nullptr, nullptr, z, emb, nullptr, nullptr,
                                     p_degNi, p_offN, p_csrN,
                                     wtL[0], gb, p_hA, nullptr, nullptr, 0, NNODES);
    k_conv<0, 0><<<gN, 128, 0, s2>>>(p_hA, nullptr, nullptr, nullptr, nullptr, nullptr,
                                     p_degNi, p_offN, p_csrN,
                                     wtL[1], gb + HID, p_hB, nullptr, nullptr, 0, NNODES);
    k_conv<0, 1><<<gN, 128, 0, s2>>>(p_hB, nullptr, nullptr, nullptr, nullptr, nullptr,
                                     p_degNi, p_offN, p_csrN,
                                     wtL[2], gb + 2 * HID, nullptr, ng, p_pool, 0, NNODES);
    k_cnt<<<cdiv(NNODES, T), T, 0, s2>>>(ng, p_cnt, 0, NNODES);
    k_cnt<<<cdiv(NEDGES, T), T, 0, s2>>>(eg, p_cnt, NB, NEDGES);
    cudaEventRecord(evNode, s2);

    // ---- line chain on main stream ----
    k_deg<<<cdiv(NEDGES2, T), T>>>(lsrc, ldst, p_degEo, NEDGES, NEDGES2);
    k_scan1<<<cdiv(NEDGES, SCAN_BS), SCAN_BS>>>(p_degEi, p_offE, p_bsumE, NEDGES);
    k_scan2<<<1, SCAN_BS>>>(p_bsumE, cdiv(NEDGES, SCAN_BS));
    k_scan3<<<cdiv(NEDGES, T), T>>>(p_offE, p_bsumE, p_curE, NEDGES);
    k_fill<<<cdiv(NEDGES2, T), T>>>(lsrc, ldst, p_degEo, p_curE, p_csrE, NEDGES2);
    k_conv<1, 0><<<gE, 128>>>(nullptr, d, nullptr, nullptr, epw, epb,
                              p_degEi, p_offE, p_csrE,
                              wtL[3], lgb, p_eA, nullptr, nullptr, 0, NEDGES);
    k_conv<0, 0><<<gE, 128>>>(p_eA, nullptr, nullptr, nullptr, nullptr, nullptr,
                              p_degEi, p_offE, p_csrE,
                              wtL[4], lgb + HID, p_eB, nullptr, nullptr, 0, NEDGES);
    k_conv<0, 1><<<gE, 128>>>(p_eB, nullptr, nullptr, nullptr, nullptr, nullptr,
                              p_degEi, p_offE, p_csrE,
                              wtL[5], lgb + 2 * HID, nullptr, eg, p_pool, 128, NEDGES);

    // ---- join + readout ----
    cudaStreamWaitEvent(0, evNode, 0);
    k_readout<<<NB, 128>>>(p_pool, p_cnt, r1w, r1b, r2w, r2b, out);
}

// round 16
// speedup vs baseline: 2.3212x; 1.0912x over previous
#include <cuda_runtime.h>
#include <cuda_fp16.h>
#include <math.h>
#include <stdint.h>

// ---------------- problem constants ----------------
#define NNODES   100000
#define NEDGES   600000
#define NEDGES2  1500000
#define HID      128
#define HF4      32
#define NB       64
#define MAXZ1    101
#define WT16_LAYER 4096   // entries per layer: 8 ks * 16 nf * 32 lanes (uint2)
#define SCAN_BS  1024

// ---------------- scratch ----------------
__device__ __half g_hA[(size_t)NNODES * HID];
__device__ __half g_hB[(size_t)NNODES * HID];
__device__ __half g_eA[(size_t)NEDGES * HID];
__device__ __half g_eB[(size_t)NEDGES * HID];

struct ZB {
    int degN[2 * NNODES];         // [out | in]
    int degE[2 * NEDGES];
    int cnt [2 * NB];
    float pool[NB * 256];
    float S1[NEDGES];             // per-line-row sum d[s]*sc[s]
    float S2[NEDGES];             // per-line-row sum sc[s]
};
__device__ ZB  g_zb;
__device__ int g_offN[NNODES];
__device__ int g_curN[NNODES];
__device__ int g_offE[NEDGES];
__device__ int g_curE[NEDGES];
__device__ int2 g_csrN[NEDGES];    // (src, rsdeg_out(src) as float bits)
__device__ int2 g_csrE[NEDGES2];
__device__ int g_bsumE[SCAN_BS];
__device__ int g_bsumN[SCAN_BS];
__device__ uint2 g_Wt16[6 * WT16_LAYER];
__device__ float g_embW[MAXZ1 * HID];   // emb @ gW[0]
__device__ float g_uv[2 * HID];         // [u = ep_w@lgW0 | v = ep_b@lgW0]

// ---------------- helpers ----------------
__device__ __forceinline__ void red_add_v2(float* addr, float x, float y) {
    asm volatile("red.global.add.v2.f32 [%0], {%1,%2};"
                 :: "l"(addr), "f"(x), "f"(y) : "memory");
}
__device__ __forceinline__ void mma_f16(float& c0, float& c1, float& c2, float& c3,
                                        uint32_t a0, uint32_t a1, uint32_t a2, uint32_t a3,
                                        uint32_t b0, uint32_t b1) {
    asm volatile("mma.sync.aligned.m16n8k16.row.col.f32.f16.f16.f32 "
                 "{%0,%1,%2,%3}, {%4,%5,%6,%7}, {%8,%9}, {%0,%1,%2,%3};"
                 : "+f"(c0), "+f"(c1), "+f"(c2), "+f"(c3)
                 : "r"(a0), "r"(a1), "r"(a2), "r"(a3), "r"(b0), "r"(b1));
}
__device__ __forceinline__ float rsdeg_i(int d) {
    return rsqrtf(fmaxf((float)d, 1.f));
}

// ---------------- small kernels ----------------
__global__ void k_zero_all() {
    long n4 = sizeof(ZB) / 16;
    float4* p = (float4*)&g_zb;
    long i = (long)blockIdx.x * blockDim.x + threadIdx.x;
    if (i < n4) p[i] = make_float4(0.f, 0.f, 0.f, 0.f);
}

__global__ void k_wt16(const float* __restrict__ gW, const float* __restrict__ lgW,
                       uint2* __restrict__ Wt) {
    int idx = blockIdx.x * blockDim.x + threadIdx.x;
    if (idx >= 6 * WT16_LAYER) return;
    int layer = idx >> 12;
    int rem = idx & 4095;
    int ks = rem >> 9;
    int rem2 = rem & 511;
    int nf = rem2 >> 5, lane = rem2 & 31;
    int g = lane >> 2, t = lane & 3;
    int n = nf * 8 + g, k0 = ks * 16 + 2 * t;
    const float* W = (layer < 3) ? (gW + (long)layer * 16384)
                                 : (lgW + (long)(layer - 3) * 16384);
    __half2 b0 = __floats2half2_rn(__ldg(W + k0 * HID + n), __ldg(W + (k0 + 1) * HID + n));
    __half2 b1 = __floats2half2_rn(__ldg(W + (k0 + 8) * HID + n), __ldg(W + (k0 + 9) * HID + n));
    Wt[idx] = make_uint2(*(uint32_t*)&b0, *(uint32_t*)&b1);
}

// u = ep_w @ lgW0, v = ep_b @ lgW0  (two 128-vectors)
__global__ void k_uv(const float* __restrict__ epw, const float* __restrict__ epb,
                     const float* __restrict__ lgW0, float* __restrict__ uv) {
    int n = threadIdx.x;          // 256 threads
    const float* vec = (n < HID) ? epw : epb;
    int nn = n & 127;
    float s = 0.f;
    for (int k = 0; k < HID; k++) s += vec[k] * __ldg(lgW0 + k * HID + nn);
    uv[(n < HID) ? nn : (HID + nn)] = s;
}

// embW = emb @ gW0  (101 x 128)
__global__ void k_embW(const float* __restrict__ emb, const float* __restrict__ gW0,
                       float* __restrict__ embW) {
    int idx = blockIdx.x * blockDim.x + threadIdx.x;
    if (idx >= MAXZ1 * HID) return;
    int r = idx >> 7, n = idx & 127;
    float s = 0.f;
    for (int k = 0; k < HID; k++) s += __ldg(emb + r * HID + k) * __ldg(gW0 + k * HID + n);
    embW[idx] = s;
}

__global__ void k_deg(const int* __restrict__ s, const int* __restrict__ t,
                      int* deg, int noff, int n) {
    int i = blockIdx.x * blockDim.x + threadIdx.x;
    if (i < n) {
        atomicAdd(deg + s[i], 1);
        atomicAdd(deg + noff + t[i], 1);
    }
}

// line layer-1 scalar aggregation: S1[t] += d[s]*sc, S2[t] += sc
__global__ void k_s12(const int* __restrict__ lsrc, const int* __restrict__ ldst,
                      const float* __restrict__ d, const int* __restrict__ degEo,
                      float* __restrict__ S1, float* __restrict__ S2, int n) {
    int i = blockIdx.x * blockDim.x + threadIdx.x;
    if (i < n) {
        int s = lsrc[i];
        float sc = rsdeg_i(__ldg(degEo + s));
        int t = ldst[i];
        atomicAdd(S1 + t, __ldg(d + s) * sc);
        atomicAdd(S2 + t, sc);
    }
}

// line layer-1 output: e1[r][n] = relu(si*(S1*u[n] + S2*v[n]) + b[n])
__global__ void k_e1(const float* __restrict__ S1, const float* __restrict__ S2,
                     const int* __restrict__ degEi, const float* __restrict__ uv,
                     const float* __restrict__ bias, __half* __restrict__ out16) {
    long gid = (long)blockIdx.x * blockDim.x + threadIdx.x;
    int r = (int)(gid >> 5), lane = (int)(gid & 31);
    if (r >= NEDGES) return;
    float si = rsdeg_i(__ldg(degEi + r));
    float s1 = __ldg(S1 + r) * si, s2 = __ldg(S2 + r) * si;
    float4 u = ((const float4*)uv)[lane];
    float4 v = ((const float4*)uv)[32 + lane];
    float4 b = ((const float4*)bias)[lane];
    float ox = fmaxf(s1 * u.x + s2 * v.x + b.x, 0.f);
    float oy = fmaxf(s1 * u.y + s2 * v.y + b.y, 0.f);
    float oz = fmaxf(s1 * u.z + s2 * v.z + b.z, 0.f);
    float ow = fmaxf(s1 * u.w + s2 * v.w + b.w, 0.f);
    __half2 h0 = __floats2half2_rn(ox, oy);
    __half2 h1 = __floats2half2_rn(oz, ow);
    *(uint2*)(out16 + (long)r * HID + lane * 4) =
        make_uint2(*(uint32_t*)&h0, *(uint32_t*)&h1);
}

// node layer-1: gather directly in embW space (no GEMM): warp per row
__global__ void k_h1(const int* __restrict__ z, const float* __restrict__ embW,
                     const int* __restrict__ degNi, const int* __restrict__ off,
                     const int2* __restrict__ csr, const float* __restrict__ bias,
                     __half* __restrict__ out16) {
    long gid = (long)blockIdx.x * blockDim.x + threadIdx.x;
    int r = (int)(gid >> 5), lane = (int)(gid & 31);
    if (r >= NNODES) return;
    int beg = __ldg(off + r), dg = __ldg(degNi + r);
    float4 acc = make_float4(0.f, 0.f, 0.f, 0.f);
    for (int j = beg; j < beg + dg; j++) {
        int2 en = __ldg(csr + j);
        float sc = __int_as_float(en.y);
        int zi = __ldg(z + en.x);
        float4 v = __ldg((const float4*)embW + (long)zi * HF4 + lane);
        acc.x += v.x * sc; acc.y += v.y * sc; acc.z += v.z * sc; acc.w += v.w * sc;
    }
    float si = rsdeg_i(dg);
    float4 b = ((const float4*)bias)[lane];
    float ox = fmaxf(acc.x * si + b.x, 0.f);
    float oy = fmaxf(acc.y * si + b.y, 0.f);
    float oz = fmaxf(acc.z * si + b.z, 0.f);
    float ow = fmaxf(acc.w * si + b.w, 0.f);
    __half2 h0 = __floats2half2_rn(ox, oy);
    __half2 h1 = __floats2half2_rn(oz, ow);
    *(uint2*)(out16 + (long)r * HID + lane * 4) =
        make_uint2(*(uint32_t*)&h0, *(uint32_t*)&h1);
}

__global__ void k_cnt(const int* __restrict__ seg, int* __restrict__ cnt,
                      int cntoff, int n) {
    __shared__ int h[NB];
    int t = threadIdx.x;
    if (t < NB) h[t] = 0;
    __syncthreads();
    int i = blockIdx.x * blockDim.x + t;
    if (i < n) atomicAdd(h + seg[i], 1);
    __syncthreads();
    if (t < NB && h[t]) atomicAdd(cnt + cntoff + t, h[t]);
}

__global__ void k_scan1(const int* __restrict__ deg, int* __restrict__ off,
                        int* __restrict__ bsum, int n) {
    __shared__ int sh[SCAN_BS];
    int t = threadIdx.x;
    int i = blockIdx.x * SCAN_BS + t;
    int v = (i < n) ? deg[i] : 0;
    sh[t] = v;
    __syncthreads();
    for (int s = 1; s < SCAN_BS; s <<= 1) {
        int add = (t >= s) ? sh[t - s] : 0;
        __syncthreads();
        sh[t] += add;
        __syncthreads();
    }
    if (i < n) off[i] = sh[t] - v;
    if (t == SCAN_BS - 1) bsum[blockIdx.x] = sh[t];
}
__global__ void k_scan2(int* bsum, int nb) {
    __shared__ int sh[SCAN_BS];
    int t = threadIdx.x;
    int v = (t < nb) ? bsum[t] : 0;
    sh[t] = v;
    __syncthreads();
    for (int s = 1; s < SCAN_BS; s <<= 1) {
        int add = (t >= s) ? sh[t - s] : 0;
        __syncthreads();
        sh[t] += add;
        __syncthreads();
    }
    if (t < nb) bsum[t] = sh[t] - v;
}
__global__ void k_scan3(int* __restrict__ off, const int* __restrict__ bsum,
                        int* __restrict__ cur, int n) {
    int i = blockIdx.x * blockDim.x + threadIdx.x;
    if (i < n) {
        int o = off[i] + bsum[i >> 10];
        off[i] = o;
        cur[i] = o;
    }
}
__global__ void k_fill(const int* __restrict__ s, const int* __restrict__ t,
                       const int* __restrict__ dego,
                       int* __restrict__ cur, int2* __restrict__ csr, int n) {
    int i = blockIdx.x * blockDim.x + threadIdx.x;
    if (i < n) {
        int si = s[i];
        float sc = rsdeg_i(__ldg(dego + si));
        int p = atomicAdd(cur + t[i], 1);
        csr[p] = make_int2(si, __float_as_int(sc));
    }
}

// ---------------- fused CSR-gather + fp16 tensor-core GEMM -----------------
// Paired-row gather; gather source = fp16 features only.
// EPI 0: store rows fp16;  EPI 1: red.add into pool (fp32)
#define XH_STRIDE 136
template<int EPI>
__global__ void __launch_bounds__(128)
k_conv(const __half* __restrict__ feat16,
       const int* __restrict__ degi,
       const int* __restrict__ off, const int2* __restrict__ csr,
       const uint2* __restrict__ Wt, const float* __restrict__ bias,
       __half* __restrict__ out16, const int* __restrict__ seg,
       float* __restrict__ pool, int coloff, int rows) {
    __shared__ __align__(16) __half Xs[64 * XH_STRIDE];
    int tid = threadIdx.x;
    int warp = tid >> 5, lane = tid & 31;
    int g = lane >> 2, tig = lane & 3;
    long r0 = (long)blockIdx.x * 64;

    // ---- phase 1: paired-row gather (8 pairs per warp) ----
    for (int rl = warp; rl < 64; rl += 8) {
        int rlA = rl, rlB = rl + 4;
        long rA = r0 + rlA, rB = r0 + rlB;
        float4 accA = make_float4(0.f, 0.f, 0.f, 0.f);
        float4 accB = make_float4(0.f, 0.f, 0.f, 0.f);
        int begA = 0, dgA = 0, begB = 0, dgB = 0;
        float siA = 0.f, siB = 0.f;
        if (rA < rows) { begA = __ldg(off + rA); dgA = __ldg(degi + rA); siA = rsdeg_i(dgA); }
        if (rB < rows) { begB = __ldg(off + rB); dgB = __ldg(degi + rB); siB = rsdeg_i(dgB); }
        int m = dgA > dgB ? dgA : dgB;
        for (int j = 0; j < m; j++) {
            bool pA = j < dgA, pB = j < dgB;
            int2 eA, eB;
            if (pA) eA = __ldg(csr + begA + j);
            if (pB) eB = __ldg(csr + begB + j);
            if (pA) {
                float sc = __int_as_float(eA.y);
                uint2 raw = __ldg((const uint2*)feat16 + (long)eA.x * 32 + lane);
                float2 f0 = __half22float2(*(__half2*)&raw.x);
                float2 f1 = __half22float2(*(__half2*)&raw.y);
                accA.x += f0.x * sc; accA.y += f0.y * sc;
                accA.z += f1.x * sc; accA.w += f1.y * sc;
            }
            if (pB) {
                float sc = __int_as_float(eB.y);
                uint2 raw = __ldg((const uint2*)feat16 + (long)eB.x * 32 + lane);
                float2 f0 = __half22float2(*(__half2*)&raw.x);
                float2 f1 = __half22float2(*(__half2*)&raw.y);
                accB.x += f0.x * sc; accB.y += f0.y * sc;
                accB.z += f1.x * sc; accB.w += f1.y * sc;
            }
        }
        __half2 a0 = __floats2half2_rn(accA.x * siA, accA.y * siA);
        __half2 a1 = __floats2half2_rn(accA.z * siA, accA.w * siA);
        *(uint2*)(Xs + rlA * XH_STRIDE + lane * 4) =
            make_uint2(*(uint32_t*)&a0, *(uint32_t*)&a1);
        __half2 b0 = __floats2half2_rn(accB.x * siB, accB.y * siB);
        __half2 b1 = __floats2half2_rn(accB.z * siB, accB.w * siB);
        *(uint2*)(Xs + rlB * XH_STRIDE + lane * 4) =
            make_uint2(*(uint32_t*)&b0, *(uint32_t*)&b1);
    }
    __syncthreads();

    // ---- phase 2: 64x128 @ 128x128 fp16 MMA (m16n8k16, fp32 accum) ----
    float acc[16][4];
#pragma unroll
    for (int nf = 0; nf < 16; nf++)
#pragma unroll
        for (int j = 0; j < 4; j++) acc[nf][j] = 0.f;

    const __half* xa = Xs + (warp * 16 + g) * XH_STRIDE + 2 * tig;
    const uint2* wt = Wt + lane;
#pragma unroll
    for (int ks = 0; ks < 8; ks++) {
        int k0 = ks * 16;
        uint32_t a0 = *(const uint32_t*)(xa + k0);
        uint32_t a1 = *(const uint32_t*)(xa + 8 * XH_STRIDE + k0);
        uint32_t a2 = *(const uint32_t*)(xa + k0 + 8);
        uint32_t a3 = *(const uint32_t*)(xa + 8 * XH_STRIDE + k0 + 8);
#pragma unroll
        for (int nf = 0; nf < 16; nf++) {
            uint2 b = __ldg(wt + (ks * 16 + nf) * 32);
            mma_f16(acc[nf][0], acc[nf][1], acc[nf][2], acc[nf][3],
                    a0, a1, a2, a3, b.x, b.y);
        }
    }

    long row0 = r0 + warp * 16 + g;
    long row1 = row0 + 8;
    int seg0 = 0, seg1 = 0;
    if (EPI == 1) {
        if (row0 < rows) seg0 = __ldg(seg + row0);
        if (row1 < rows) seg1 = __ldg(seg + row1);
    }
#pragma unroll
    for (int nf = 0; nf < 16; nf++) {
        int n0 = nf * 8 + 2 * tig;
        float b0 = __ldg(bias + n0), b1 = __ldg(bias + n0 + 1);
        if (row0 < rows) {
            float ox = fmaxf(acc[nf][0] + b0, 0.f);
            float oy = fmaxf(acc[nf][1] + b1, 0.f);
            if (EPI == 0) *(__half2*)(out16 + row0 * HID + n0) = __floats2half2_rn(ox, oy);
            else red_add_v2(pool + (long)seg0 * 256 + coloff + n0, ox, oy);
        }
        if (row1 < rows) {
            float ox = fmaxf(acc[nf][2] + b0, 0.f);
            float oy = fmaxf(acc[nf][3] + b1, 0.f);
            if (EPI == 0) *(__half2*)(out16 + row1 * HID + n0) = __floats2half2_rn(ox, oy);
            else red_add_v2(pool + (long)seg1 * 256 + coloff + n0, ox, oy);
        }
    }
}

// final MLP
__global__ void k_readout(const float* __restrict__ pool, const int* __restrict__ cnt,
                          const float* __restrict__ r1w, const float* __restrict__ r1b,
                          const float* __restrict__ r2w, const float* __restrict__ r2b,
                          float* __restrict__ out) {
    __shared__ float x[256];
    __shared__ float redbuf[128];
    int g = blockIdx.x, tid = threadIdx.x;
    float cn = fmaxf((float)cnt[g], 1.f);
    float ce = fmaxf((float)cnt[NB + g], 1.f);
    x[tid]       = pool[g * 256 + tid] / cn;
    x[128 + tid] = pool[g * 256 + 128 + tid] / ce;
    __syncthreads();
    float a = r1b[tid];
#pragma unroll 8
    for (int k = 0; k < 256; k++) a += x[k] * r1w[k * 128 + tid];
    float sig = 1.f / (1.f + expf(-a));
    float p = a * sig * r2w[tid];
    redbuf[tid] = p;
    __syncthreads();
    for (int s = 64; s > 0; s >>= 1) {
        if (tid < s) redbuf[tid] += redbuf[tid + s];
        __syncthreads();
    }
    if (tid == 0) out[g] = redbuf[0] + r2b[0];
}

// ---------------- launch ----------------
static inline int cdiv(long a, long b) { return (int)((a + b - 1) / b); }

extern "C" void kernel_launch(void* const* d_in, const int* in_sizes, int n_in,
                              void* d_out, int out_size) {
    const int*   z    = (const int*)  d_in[0];
    const float* d    = (const float*)d_in[1];
    const int*   src  = (const int*)  d_in[2];
    const int*   dst  = (const int*)  d_in[3];
    const int*   lsrc = (const int*)  d_in[4];
    const int*   ldst = (const int*)  d_in[5];
    const int*   ng   = (const int*)  d_in[6];
    const int*   eg   = (const int*)  d_in[7];
    const float* emb  = (const float*)d_in[8];
    const float* epw  = (const float*)d_in[9];
    const float* epb  = (const float*)d_in[10];
    const float* gW   = (const float*)d_in[11];
    const float* gb   = (const float*)d_in[12];
    const float* lgW  = (const float*)d_in[13];
    const float* lgb  = (const float*)d_in[14];
    const float* r1w  = (const float*)d_in[15];
    const float* r1b  = (const float*)d_in[16];
    const float* r2w  = (const float*)d_in[17];
    const float* r2b  = (const float*)d_in[18];
    float* out = (float*)d_out;

    __half *p_hA, *p_hB, *p_eA, *p_eB;
    uint2 *p_Wt16;
    float *p_embW, *p_uv;
    int *p_offN, *p_curN, *p_offE, *p_curE, *p_bsumE, *p_bsumN;
    int2 *p_csrN, *p_csrE;
    ZB* p_zb;
    cudaGetSymbolAddress((void**)&p_hA,    g_hA);
    cudaGetSymbolAddress((void**)&p_hB,    g_hB);
    cudaGetSymbolAddress((void**)&p_eA,    g_eA);
    cudaGetSymbolAddress((void**)&p_eB,    g_eB);
    cudaGetSymbolAddress((void**)&p_zb,    g_zb);
    cudaGetSymbolAddress((void**)&p_offN,  g_offN);
    cudaGetSymbolAddress((void**)&p_curN,  g_curN);
    cudaGetSymbolAddress((void**)&p_offE,  g_offE);
    cudaGetSymbolAddress((void**)&p_curE,  g_curE);
    cudaGetSymbolAddress((void**)&p_csrN,  g_csrN);
    cudaGetSymbolAddress((void**)&p_csrE,  g_csrE);
    cudaGetSymbolAddress((void**)&p_bsumE, g_bsumE);
    cudaGetSymbolAddress((void**)&p_bsumN, g_bsumN);
    cudaGetSymbolAddress((void**)&p_Wt16,  g_Wt16);
    cudaGetSymbolAddress((void**)&p_embW,  g_embW);
    cudaGetSymbolAddress((void**)&p_uv,    g_uv);

    int* p_degNo = p_zb->degN;
    int* p_degNi = p_zb->degN + NNODES;
    int* p_degEo = p_zb->degE;
    int* p_degEi = p_zb->degE + NEDGES;
    int* p_cnt   = p_zb->cnt;
    float* p_pool = p_zb->pool;
    float* p_S1   = p_zb->S1;
    float* p_S2   = p_zb->S2;

    const uint2* wtL[6];
    for (int l = 0; l < 6; l++) wtL[l] = p_Wt16 + (long)l * WT16_LAYER;

    const int T = 256;
    const int gE = cdiv(NEDGES, 64), gN = cdiv(NNODES, 64);

    cudaStream_t s2;
    cudaStreamCreateWithFlags(&s2, cudaStreamNonBlocking);
    cudaEvent_t evRoot, evNode;
    cudaEventCreateWithFlags(&evRoot, cudaEventDisableTiming);
    cudaEventCreateWithFlags(&evNode, cudaEventDisableTiming);

    // ---- common prologue (main stream) ----
    k_zero_all<<<cdiv(sizeof(ZB) / 16, T), T>>>();
    k_wt16<<<cdiv(6 * WT16_LAYER, T), T>>>(gW, lgW, p_Wt16);
    k_uv<<<1, 256>>>(epw, epb, lgW, p_uv);
    k_embW<<<cdiv(MAXZ1 * HID, T), T>>>(emb, gW, p_embW);
    cudaEventRecord(evRoot, 0);

    // ---- node chain on s2 ----
    cudaStreamWaitEvent(s2, evRoot, 0);
    k_deg<<<cdiv(NEDGES, T), T, 0, s2>>>(src, dst, p_degNo, NNODES, NEDGES);
    k_scan1<<<cdiv(NNODES, SCAN_BS), SCAN_BS, 0, s2>>>(p_degNi, p_offN, p_bsumN, NNODES);
    k_scan2<<<1, SCAN_BS, 0, s2>>>(p_bsumN, cdiv(NNODES, SCAN_BS));
    k_scan3<<<cdiv(NNODES, T), T, 0, s2>>>(p_offN, p_bsumN, p_curN, NNODES);
    k_fill<<<cdiv(NEDGES, T), T, 0, s2>>>(src, dst, p_degNo, p_curN, p_csrN, NEDGES);
    k_h1<<<cdiv((long)NNODES * 32, T), T, 0, s2>>>(z, p_embW, p_degNi, p_offN, p_csrN,
                                                   gb, p_hA);
    k_conv<0><<<gN, 128, 0, s2>>>(p_hA, p_degNi, p_offN, p_csrN,
                                  wtL[1], gb + HID, p_hB, nullptr, nullptr, 0, NNODES);
    k_conv<1><<<gN, 128, 0, s2>>>(p_hB, p_degNi, p_offN, p_csrN,
                                  wtL[2], gb + 2 * HID, nullptr, ng, p_pool, 0, NNODES);
    k_cnt<<<cdiv(NNODES, T), T, 0, s2>>>(ng, p_cnt, 0, NNODES);
    k_cnt<<<cdiv(NEDGES, T), T, 0, s2>>>(eg, p_cnt, NB, NEDGES);
    cudaEventRecord(evNode, s2);

    // ---- line chain on main stream ----
    k_deg<<<cdiv(NEDGES2, T), T>>>(lsrc, ldst, p_degEo, NEDGES, NEDGES2);
    k_s12<<<cdiv(NEDGES2, T), T>>>(lsrc, ldst, d, p_degEo, p_S1, p_S2, NEDGES2);
    k_e1<<<cdiv((long)NEDGES * 32, T), T>>>(p_S1, p_S2, p_degEi, p_uv, lgb, p_eA);
    k_scan1<<<cdiv(NEDGES, SCAN_BS), SCAN_BS>>>(p_degEi, p_offE, p_bsumE, NEDGES);
    k_scan2<<<1, SCAN_BS>>>(p_bsumE, cdiv(NEDGES, SCAN_BS));
    k_scan3<<<cdiv(NEDGES, T), T>>>(p_offE, p_bsumE, p_curE, NEDGES);
    k_fill<<<cdiv(NEDGES2, T), T>>>(lsrc, ldst, p_degEo, p_curE, p_csrE, NEDGES2);
    k_conv<0><<<gE, 128>>>(p_eA, p_degEi, p_offE, p_csrE,
                           wtL[4], lgb + HID, p_eB, nullptr, nullptr, 0, NEDGES);
    k_conv<1><<<gE, 128>>>(p_eB, p_degEi, p_offE, p_csrE,
                           wtL[5], lgb + 2 * HID, nullptr, eg, p_pool, 128, NEDGES);

    // ---- join + readout ----
    cudaStreamWaitEvent(0, evNode, 0);
    k_readout<<<NB, 128>>>(p_pool, p_cnt, r1w, r1b, r2w, r2b, out);
}